// round 3
// baseline (speedup 1.0000x reference)
#include <cuda_runtime.h>
#include <cstdint>

#define N_NODES  100000
#define N_EDGES  3200000
#define N_GRAPHS 256
#define IN_DIM   128
#define HID_DIM  128
#define OUT_DIM  64

// ---------------- scratch (static device globals; no allocation) ----------------
__device__ float g_agg1[(size_t)N_NODES * IN_DIM];    // 51.2 MB
__device__ float g_h   [(size_t)N_NODES * HID_DIM];   // 51.2 MB
__device__ float g_agg2[(size_t)N_NODES * HID_DIM];   // 51.2 MB
__device__ float g_deg [N_NODES];
__device__ float g_poolL[N_GRAPHS * HID_DIM];
__device__ float g_poolR[N_GRAPHS * HID_DIM];
__device__ float g_cnt [N_GRAPHS];
__device__ float g_WlT[IN_DIM * HID_DIM];             // WlT[k][o] = Wl1[o][k]
__device__ float g_WrT[IN_DIM * HID_DIM];
__device__ int   g_is64;                              // 1 if indices are int64, 0 if int32

// index accessor honoring runtime-detected dtype
__device__ __forceinline__ int load_idx(const void* p, long long i, int is64) {
    if (is64) return (int)((const long long*)p)[i];
    return ((const int*)p)[i];
}

// ---------------- kernels ----------------

// Detect whether the edge buffer is int64 or int32.
// If int64: every odd int32 word (hi word of a value < 2^31) is 0 across the
// whole buffer. If int32 (random indices in [0,1e5)), some of 2048 sampled
// odd words are nonzero with probability ~1 - 1e-5^... (certain in practice).
__global__ void k_detect(const int* __restrict__ ei32) {
    __shared__ int any_nonzero;
    if (threadIdx.x == 0) any_nonzero = 0;
    __syncthreads();
    // sample odd positions spread across the buffer (2*N_EDGES logical elems)
    for (int j = threadIdx.x; j < 2048; j += blockDim.x) {
        long long pos = 2LL * ((long long)j * 1553LL + 1) + 1;  // odd indices
        if (pos < 2LL * N_EDGES * 2) {
            if (ei32[pos] != 0) atomicOr(&any_nonzero, 1);
        }
    }
    __syncthreads();
    if (threadIdx.x == 0) g_is64 = any_nonzero ? 0 : 1;
}

__global__ void k_zero() {
    int i = blockIdx.x * blockDim.x + threadIdx.x;
    int stride = gridDim.x * blockDim.x;
    const float4 z = make_float4(0.f, 0.f, 0.f, 0.f);
    float4* a1 = (float4*)g_agg1;
    float4* a2 = (float4*)g_agg2;
    for (int j = i; j < N_NODES * 32; j += stride) { a1[j] = z; a2[j] = z; }
    for (int j = i; j < N_NODES; j += stride) g_deg[j] = 0.f;
    float4* pl = (float4*)g_poolL;
    float4* pr = (float4*)g_poolR;
    for (int j = i; j < N_GRAPHS * 32; j += stride) { pl[j] = z; pr[j] = z; }
    if (i < N_GRAPHS) g_cnt[i] = 0.f;
}

__global__ void k_transpose(const float* __restrict__ Wl, const float* __restrict__ Wr) {
    int i = blockIdx.x * blockDim.x + threadIdx.x;   // 0 .. 16383
    if (i < IN_DIM * HID_DIM) {
        int o = i >> 7, k = i & 127;
        g_WlT[k * 128 + o] = Wl[i];
        g_WrT[k * 128 + o] = Wr[i];
    }
}

// warp-per-edge scatter-add: out[dst] += feat[src]  (128 floats = 32 lanes x float4)
// pass==1: feat=x,  out=g_agg1, counts degree.  pass==2: feat=g_h, out=g_agg2.
__global__ void k_scatter(const float4* __restrict__ xin,
                          const void* __restrict__ ei,   // [2, E] src then dst
                          int pass) {
    const int is64 = g_is64;
    const float4* feat = (pass == 1) ? xin : (const float4*)g_h;
    float* outp = (pass == 1) ? g_agg1 : g_agg2;
    int lane = threadIdx.x & 31;
    int warp = (blockIdx.x * blockDim.x + threadIdx.x) >> 5;
    int nwarps = (gridDim.x * blockDim.x) >> 5;
    for (int e = warp; e < N_EDGES; e += nwarps) {
        int s = load_idx(ei, e, is64);
        int d = load_idx(ei, (long long)N_EDGES + e, is64);
        // safety clamp (branch-free, nearly free; protects against any residual
        // dtype surprise turning into an illegal access)
        s = min(max(s, 0), N_NODES - 1);
        d = min(max(d, 0), N_NODES - 1);
        float4 v = __ldg(&feat[(size_t)s * 32 + lane]);
        float4* p = ((float4*)outp) + (size_t)d * 32 + lane;
        asm volatile("red.global.add.v4.f32 [%0], {%1,%2,%3,%4};"
                     :: "l"(p), "f"(v.x), "f"(v.y), "f"(v.z), "f"(v.w) : "memory");
        if (pass == 1 && lane == 0) atomicAdd(&g_deg[d], 1.0f);
    }
}

// fused layer-1: h = relu( (agg1/max(deg,1)) @ Wl1^T + x @ Wr1^T + b1 )
// block = 256 threads, 32 nodes; thread tile = 2 nodes x 8 outs.
__global__ void k_gemm1(const float4* __restrict__ x4, const float* __restrict__ b1) {
    __shared__ float sA[128 * 36];   // [k][node], padded stride 36
    __shared__ float sX[128 * 36];
    __shared__ float sr[32];

    int tid = threadIdx.x;
    int n0 = blockIdx.x * 32;

    if (tid < 32) {
        int n = n0 + tid;
        sr[tid] = (n < N_NODES) ? (1.0f / fmaxf(g_deg[n], 1.0f)) : 0.0f;
    }
    __syncthreads();

    // fill transposed operand tiles (32 nodes x 128 k), float4 granularity
    for (int i = tid; i < 32 * 32; i += 256) {
        int n = i >> 5, k4 = i & 31;
        float4 a = make_float4(0.f, 0.f, 0.f, 0.f);
        float4 xx = a;
        if (n0 + n < N_NODES) {
            a = ((const float4*)g_agg1)[(size_t)(n0 + n) * 32 + k4];
            float r = sr[n];
            a.x *= r; a.y *= r; a.z *= r; a.w *= r;
            xx = __ldg(&x4[(size_t)(n0 + n) * 32 + k4]);
        }
        int k = k4 * 4;
        sA[(k + 0) * 36 + n] = a.x;  sA[(k + 1) * 36 + n] = a.y;
        sA[(k + 2) * 36 + n] = a.z;  sA[(k + 3) * 36 + n] = a.w;
        sX[(k + 0) * 36 + n] = xx.x; sX[(k + 1) * 36 + n] = xx.y;
        sX[(k + 2) * 36 + n] = xx.z; sX[(k + 3) * 36 + n] = xx.w;
    }
    __syncthreads();

    int og = tid & 15;   // outs 8*og .. 8*og+7
    int ng = tid >> 4;   // nodes 2*ng, 2*ng+1

    float acc[2][8];
#pragma unroll
    for (int i = 0; i < 2; i++)
#pragma unroll
        for (int j = 0; j < 8; j++) acc[i][j] = 0.f;

    const float4* WlT4 = (const float4*)g_WlT;
    const float4* WrT4 = (const float4*)g_WrT;

#pragma unroll 2
    for (int k = 0; k < 128; k++) {
        float2 av = *(const float2*)&sA[k * 36 + 2 * ng];
        float2 xv = *(const float2*)&sX[k * 36 + 2 * ng];
        float4 wl0 = __ldg(&WlT4[k * 32 + 2 * og]);
        float4 wl1 = __ldg(&WlT4[k * 32 + 2 * og + 1]);
        float4 wr0 = __ldg(&WrT4[k * 32 + 2 * og]);
        float4 wr1 = __ldg(&WrT4[k * 32 + 2 * og + 1]);
        float wl[8] = {wl0.x, wl0.y, wl0.z, wl0.w, wl1.x, wl1.y, wl1.z, wl1.w};
        float wr[8] = {wr0.x, wr0.y, wr0.z, wr0.w, wr1.x, wr1.y, wr1.z, wr1.w};
        float a[2] = {av.x, av.y};
        float xr[2] = {xv.x, xv.y};
#pragma unroll
        for (int i = 0; i < 2; i++)
#pragma unroll
            for (int j = 0; j < 8; j++)
                acc[i][j] += a[i] * wl[j] + xr[i] * wr[j];
    }

    float bias[8];
#pragma unroll
    for (int j = 0; j < 8; j++) bias[j] = __ldg(&b1[8 * og + j]);

#pragma unroll
    for (int i = 0; i < 2; i++) {
        int n = n0 + 2 * ng + i;
        if (n < N_NODES) {
            float4 o0, o1;
            o0.x = fmaxf(acc[i][0] + bias[0], 0.f);
            o0.y = fmaxf(acc[i][1] + bias[1], 0.f);
            o0.z = fmaxf(acc[i][2] + bias[2], 0.f);
            o0.w = fmaxf(acc[i][3] + bias[3], 0.f);
            o1.x = fmaxf(acc[i][4] + bias[4], 0.f);
            o1.y = fmaxf(acc[i][5] + bias[5], 0.f);
            o1.z = fmaxf(acc[i][6] + bias[6], 0.f);
            o1.w = fmaxf(acc[i][7] + bias[7], 0.f);
            float4* hp = ((float4*)g_h) + (size_t)n * 32 + 2 * og;
            hp[0] = o0;
            hp[1] = o1;
        }
    }
}

// pool: poolL[g] += agg2[n]/max(deg,1); poolR[g] += h[n]; cnt[g] += 1  (warp per node)
__global__ void k_pool(const void* __restrict__ batch) {
    const int is64 = g_is64;
    int lane = threadIdx.x & 31;
    int warp = (blockIdx.x * blockDim.x + threadIdx.x) >> 5;
    int nwarps = (gridDim.x * blockDim.x) >> 5;
    for (int n = warp; n < N_NODES; n += nwarps) {
        int g = load_idx(batch, n, is64);
        g = min(max(g, 0), N_GRAPHS - 1);
        float r = 1.0f / fmaxf(g_deg[n], 1.0f);
        float4 a = ((const float4*)g_agg2)[(size_t)n * 32 + lane];
        a.x *= r; a.y *= r; a.z *= r; a.w *= r;
        float4* pL = ((float4*)g_poolL) + g * 32 + lane;
        asm volatile("red.global.add.v4.f32 [%0], {%1,%2,%3,%4};"
                     :: "l"(pL), "f"(a.x), "f"(a.y), "f"(a.z), "f"(a.w) : "memory");
        float4 hv = ((const float4*)g_h)[(size_t)n * 32 + lane];
        float4* pR = ((float4*)g_poolR) + g * 32 + lane;
        asm volatile("red.global.add.v4.f32 [%0], {%1,%2,%3,%4};"
                     :: "l"(pR), "f"(hv.x), "f"(hv.y), "f"(hv.z), "f"(hv.w) : "memory");
        if (lane == 0) atomicAdd(&g_cnt[g], 1.0f);
    }
}

// final: out[g][o] = ( poolL[g]@Wl2[o]^T + poolR[g]@Wr2[o]^T ) / max(cnt,1) + b2[o]
__global__ void k_final(const float* __restrict__ Wl2, const float* __restrict__ Wr2,
                        const float* __restrict__ b2, float* __restrict__ out) {
    __shared__ float pl[128];
    __shared__ float pr[128];
    int g = blockIdx.x;
    int t = threadIdx.x;   // 64 threads = one output each
    pl[t]      = g_poolL[g * 128 + t];
    pl[t + 64] = g_poolL[g * 128 + t + 64];
    pr[t]      = g_poolR[g * 128 + t];
    pr[t + 64] = g_poolR[g * 128 + t + 64];
    __syncthreads();
    float c = fmaxf(g_cnt[g], 1.0f);
    float acc = 0.f;
    const float4* wl4 = (const float4*)&Wl2[t * 128];
    const float4* wr4 = (const float4*)&Wr2[t * 128];
#pragma unroll 8
    for (int k4 = 0; k4 < 32; k4++) {
        float4 wl = __ldg(&wl4[k4]);
        float4 wr = __ldg(&wr4[k4]);
        int k = 4 * k4;
        acc += pl[k]     * wl.x + pl[k + 1] * wl.y + pl[k + 2] * wl.z + pl[k + 3] * wl.w;
        acc += pr[k]     * wr.x + pr[k + 1] * wr.y + pr[k + 2] * wr.z + pr[k + 3] * wr.w;
    }
    out[g * 64 + t] = acc / c + __ldg(&b2[t]);
}

// ---------------- launch ----------------
extern "C" void kernel_launch(void* const* d_in, const int* in_sizes, int n_in,
                              void* d_out, int out_size) {
    const float* x     = (const float*)d_in[0];
    const void*  ei    = d_in[1];
    const void*  batch = d_in[2];
    const float* Wl1   = (const float*)d_in[3];
    const float* Wr1   = (const float*)d_in[4];
    const float* b1    = (const float*)d_in[5];
    const float* Wl2   = (const float*)d_in[6];
    const float* Wr2   = (const float*)d_in[7];
    const float* b2    = (const float*)d_in[8];
    float* out = (float*)d_out;

    k_detect<<<1, 256>>>((const int*)ei);
    k_zero<<<2048, 256>>>();
    k_transpose<<<64, 256>>>(Wl1, Wr1);

    // layer 1 aggregation:  agg1[d] += x[s], deg[d] += 1
    k_scatter<<<2048, 256>>>((const float4*)x, ei, 1);

    // h = relu((agg1/deg) @ Wl1^T + x @ Wr1^T + b1)
    k_gemm1<<<(N_NODES + 31) / 32, 256>>>((const float4*)x, b1);

    // layer 2 aggregation: agg2[d] += h[s]
    k_scatter<<<2048, 256>>>((const float4*)x, ei, 2);

    // pool to [256,128] BEFORE applying Wl2/Wr2 (linearity)
    k_pool<<<(N_NODES * 32 + 255) / 256, 256>>>(batch);

    // tiny final GEMMs [256,128]x[128,64]
    k_final<<<N_GRAPHS, 64>>>(Wl2, Wr2, b2, out);
}

// round 4
// speedup vs baseline: 1.3656x; 1.3656x over previous
#include <cuda_runtime.h>
#include <cstdint>

#define N_NODES  100000
#define N_EDGES  3200000
#define N_GRAPHS 256
#define IN_DIM   128
#define HID_DIM  128
#define OUT_DIM  64

// ---------------- scratch (static device globals; no allocation) ----------------
__device__ float g_agg1[(size_t)N_NODES * IN_DIM];    // 51.2 MB (stores MEAN directly)
__device__ float g_h   [(size_t)N_NODES * HID_DIM];   // 51.2 MB
__device__ int   g_count [N_NODES];                   // histogram / degree
__device__ int   g_rowptr[N_NODES + 1];
__device__ int   g_wcur  [N_NODES];                   // fill cursors
__device__ int   g_col   [N_EDGES];                   // CSR col = src of edge, grouped by dst
__device__ float g_poolL[N_GRAPHS * HID_DIM];
__device__ float g_poolR[N_GRAPHS * HID_DIM];
__device__ float g_cnt [N_GRAPHS];
__device__ float g_WlT[IN_DIM * HID_DIM];             // WlT[k][o] = Wl1[o][k]
__device__ float g_WrT[IN_DIM * HID_DIM];
__device__ int   g_is64;                              // 1 if indices are int64, 0 if int32

__device__ __forceinline__ int load_idx(const void* p, long long i, int is64) {
    if (is64) return (int)((const long long*)p)[i];
    return ((const int*)p)[i];
}

// ---------------- kernels ----------------

// Detect int64 vs int32 index buffers (JAX x64-disabled silently gives int32).
__global__ void k_detect(const int* __restrict__ ei32) {
    __shared__ int any_nonzero;
    if (threadIdx.x == 0) any_nonzero = 0;
    __syncthreads();
    for (int j = threadIdx.x; j < 2048; j += blockDim.x) {
        long long pos = 2LL * ((long long)j * 1553LL + 1) + 1;  // odd words
        if (pos < 2LL * N_EDGES * 2) {
            if (ei32[pos] != 0) atomicOr(&any_nonzero, 1);
        }
    }
    __syncthreads();
    if (threadIdx.x == 0) g_is64 = any_nonzero ? 0 : 1;
}

// zero only the small stuff: histogram + pool buffers + cnt
__global__ void k_zero_small() {
    int i = blockIdx.x * blockDim.x + threadIdx.x;
    int stride = gridDim.x * blockDim.x;
    for (int j = i; j < N_NODES; j += stride) g_count[j] = 0;
    for (int j = i; j < N_GRAPHS * HID_DIM; j += stride) { g_poolL[j] = 0.f; g_poolR[j] = 0.f; }
    if (i < N_GRAPHS) g_cnt[i] = 0.f;
}

__global__ void k_transpose(const float* __restrict__ Wl, const float* __restrict__ Wr) {
    int i = blockIdx.x * blockDim.x + threadIdx.x;
    if (i < IN_DIM * HID_DIM) {
        int o = i >> 7, k = i & 127;
        g_WlT[k * 128 + o] = Wl[i];
        g_WrT[k * 128 + o] = Wr[i];
    }
}

// CSR build step 1: histogram of dst
__global__ void k_hist(const void* __restrict__ ei) {
    const int is64 = g_is64;
    int i = blockIdx.x * blockDim.x + threadIdx.x;
    int stride = gridDim.x * blockDim.x;
    for (int e = i; e < N_EDGES; e += stride) {
        int d = load_idx(ei, (long long)N_EDGES + e, is64);
        d = min(max(d, 0), N_NODES - 1);
        atomicAdd(&g_count[d], 1);
    }
}

// CSR build step 2: exclusive scan (single block, 1024 threads, chunked)
__global__ void k_scan() {
    __shared__ int ssum[1024];
    int t = threadIdx.x;
    const int CH = (N_NODES + 1023) / 1024;   // 98
    int base = t * CH;
    int s = 0;
    for (int i = 0; i < CH; i++) {
        int n = base + i;
        if (n < N_NODES) s += g_count[n];
    }
    ssum[t] = s;
    __syncthreads();
    // Hillis-Steele inclusive scan
    for (int off = 1; off < 1024; off <<= 1) {
        int v = (t >= off) ? ssum[t - off] : 0;
        __syncthreads();
        ssum[t] += v;
        __syncthreads();
    }
    int run = ssum[t] - s;   // exclusive prefix for this chunk
    for (int i = 0; i < CH; i++) {
        int n = base + i;
        if (n < N_NODES) {
            int c = g_count[n];
            g_rowptr[n] = run;
            g_wcur[n]   = run;
            run += c;
        }
    }
    if (t == 1023) g_rowptr[N_NODES] = run;
}

// CSR build step 3: place src ids grouped by dst
__global__ void k_fill(const void* __restrict__ ei) {
    const int is64 = g_is64;
    int i = blockIdx.x * blockDim.x + threadIdx.x;
    int stride = gridDim.x * blockDim.x;
    for (int e = i; e < N_EDGES; e += stride) {
        int s = load_idx(ei, e, is64);
        int d = load_idx(ei, (long long)N_EDGES + e, is64);
        s = min(max(s, 0), N_NODES - 1);
        d = min(max(d, 0), N_NODES - 1);
        int pos = atomicAdd(&g_wcur[d], 1);
        g_col[pos] = s;
    }
}

// layer-1 aggregation, gather-only (warp per node): g_agg1[n] = mean_{s in N(n)} x[s]
__global__ void k_agg1(const float4* __restrict__ x4) {
    int lane = threadIdx.x & 31;
    int warp = (blockIdx.x * blockDim.x + threadIdx.x) >> 5;
    if (warp >= N_NODES) return;
    int n = warp;
    int beg = g_rowptr[n], end = g_rowptr[n + 1];
    float4 acc = make_float4(0.f, 0.f, 0.f, 0.f);
    for (int e0 = beg; e0 < end; e0 += 32) {
        int myc = (e0 + lane < end) ? g_col[e0 + lane] : 0;
        int m = min(32, end - e0);
        #pragma unroll 4
        for (int j = 0; j < m; j++) {
            int s = __shfl_sync(0xffffffff, myc, j);
            float4 v = __ldg(&x4[(size_t)s * 32 + lane]);
            acc.x += v.x; acc.y += v.y; acc.z += v.z; acc.w += v.w;
        }
    }
    float r = 1.0f / fmaxf((float)(end - beg), 1.0f);
    acc.x *= r; acc.y *= r; acc.z *= r; acc.w *= r;
    ((float4*)g_agg1)[(size_t)n * 32 + lane] = acc;
}

// fused layer-1: h = relu( agg1 @ Wl1^T + x @ Wr1^T + b1 )  (agg1 is already the mean)
__global__ void k_gemm1(const float4* __restrict__ x4, const float* __restrict__ b1) {
    __shared__ float sA[128 * 36];   // [k][node], padded stride 36
    __shared__ float sX[128 * 36];

    int tid = threadIdx.x;
    int n0 = blockIdx.x * 32;

    for (int i = tid; i < 32 * 32; i += 256) {
        int n = i >> 5, k4 = i & 31;
        float4 a = make_float4(0.f, 0.f, 0.f, 0.f);
        float4 xx = a;
        if (n0 + n < N_NODES) {
            a  = ((const float4*)g_agg1)[(size_t)(n0 + n) * 32 + k4];
            xx = __ldg(&x4[(size_t)(n0 + n) * 32 + k4]);
        }
        int k = k4 * 4;
        sA[(k + 0) * 36 + n] = a.x;  sA[(k + 1) * 36 + n] = a.y;
        sA[(k + 2) * 36 + n] = a.z;  sA[(k + 3) * 36 + n] = a.w;
        sX[(k + 0) * 36 + n] = xx.x; sX[(k + 1) * 36 + n] = xx.y;
        sX[(k + 2) * 36 + n] = xx.z; sX[(k + 3) * 36 + n] = xx.w;
    }
    __syncthreads();

    int og = tid & 15;   // outs 8*og .. 8*og+7
    int ng = tid >> 4;   // nodes 2*ng, 2*ng+1

    float acc[2][8];
#pragma unroll
    for (int i = 0; i < 2; i++)
#pragma unroll
        for (int j = 0; j < 8; j++) acc[i][j] = 0.f;

    const float4* WlT4 = (const float4*)g_WlT;
    const float4* WrT4 = (const float4*)g_WrT;

#pragma unroll 2
    for (int k = 0; k < 128; k++) {
        float2 av = *(const float2*)&sA[k * 36 + 2 * ng];
        float2 xv = *(const float2*)&sX[k * 36 + 2 * ng];
        float4 wl0 = __ldg(&WlT4[k * 32 + 2 * og]);
        float4 wl1 = __ldg(&WlT4[k * 32 + 2 * og + 1]);
        float4 wr0 = __ldg(&WrT4[k * 32 + 2 * og]);
        float4 wr1 = __ldg(&WrT4[k * 32 + 2 * og + 1]);
        float wl[8] = {wl0.x, wl0.y, wl0.z, wl0.w, wl1.x, wl1.y, wl1.z, wl1.w};
        float wr[8] = {wr0.x, wr0.y, wr0.z, wr0.w, wr1.x, wr1.y, wr1.z, wr1.w};
        float a[2] = {av.x, av.y};
        float xr[2] = {xv.x, xv.y};
#pragma unroll
        for (int i = 0; i < 2; i++)
#pragma unroll
            for (int j = 0; j < 8; j++)
                acc[i][j] += a[i] * wl[j] + xr[i] * wr[j];
    }

    float bias[8];
#pragma unroll
    for (int j = 0; j < 8; j++) bias[j] = __ldg(&b1[8 * og + j]);

#pragma unroll
    for (int i = 0; i < 2; i++) {
        int n = n0 + 2 * ng + i;
        if (n < N_NODES) {
            float4 o0, o1;
            o0.x = fmaxf(acc[i][0] + bias[0], 0.f);
            o0.y = fmaxf(acc[i][1] + bias[1], 0.f);
            o0.z = fmaxf(acc[i][2] + bias[2], 0.f);
            o0.w = fmaxf(acc[i][3] + bias[3], 0.f);
            o1.x = fmaxf(acc[i][4] + bias[4], 0.f);
            o1.y = fmaxf(acc[i][5] + bias[5], 0.f);
            o1.z = fmaxf(acc[i][6] + bias[6], 0.f);
            o1.w = fmaxf(acc[i][7] + bias[7], 0.f);
            float4* hp = ((float4*)g_h) + (size_t)n * 32 + 2 * og;
            hp[0] = o0;
            hp[1] = o1;
        }
    }
}

// layer-2 aggregation fused with pooling (warp per node):
//   agg2 = mean_{s in N(n)} h[s]  (registers only)
//   poolL[batch[n]] += agg2 ;  poolR[batch[n]] += h[n] ;  cnt[batch[n]] += 1
__global__ void k_agg2pool(const void* __restrict__ batch) {
    const int is64 = g_is64;
    int lane = threadIdx.x & 31;
    int warp = (blockIdx.x * blockDim.x + threadIdx.x) >> 5;
    if (warp >= N_NODES) return;
    int n = warp;
    int beg = g_rowptr[n], end = g_rowptr[n + 1];
    float4 acc = make_float4(0.f, 0.f, 0.f, 0.f);
    const float4* h4 = (const float4*)g_h;
    for (int e0 = beg; e0 < end; e0 += 32) {
        int myc = (e0 + lane < end) ? g_col[e0 + lane] : 0;
        int m = min(32, end - e0);
        #pragma unroll 4
        for (int j = 0; j < m; j++) {
            int s = __shfl_sync(0xffffffff, myc, j);
            float4 v = __ldg(&h4[(size_t)s * 32 + lane]);
            acc.x += v.x; acc.y += v.y; acc.z += v.z; acc.w += v.w;
        }
    }
    float r = 1.0f / fmaxf((float)(end - beg), 1.0f);
    acc.x *= r; acc.y *= r; acc.z *= r; acc.w *= r;

    int g = load_idx(batch, n, is64);
    g = min(max(g, 0), N_GRAPHS - 1);

    float4* pL = ((float4*)g_poolL) + g * 32 + lane;
    asm volatile("red.global.add.v4.f32 [%0], {%1,%2,%3,%4};"
                 :: "l"(pL), "f"(acc.x), "f"(acc.y), "f"(acc.z), "f"(acc.w) : "memory");
    float4 hv = __ldg(&h4[(size_t)n * 32 + lane]);
    float4* pR = ((float4*)g_poolR) + g * 32 + lane;
    asm volatile("red.global.add.v4.f32 [%0], {%1,%2,%3,%4};"
                 :: "l"(pR), "f"(hv.x), "f"(hv.y), "f"(hv.z), "f"(hv.w) : "memory");
    if (lane == 0) atomicAdd(&g_cnt[g], 1.0f);
}

// final: out[g][o] = ( poolL[g]@Wl2[o]^T + poolR[g]@Wr2[o]^T ) / max(cnt,1) + b2[o]
__global__ void k_final(const float* __restrict__ Wl2, const float* __restrict__ Wr2,
                        const float* __restrict__ b2, float* __restrict__ out) {
    __shared__ float pl[128];
    __shared__ float pr[128];
    int g = blockIdx.x;
    int t = threadIdx.x;   // 64 threads
    pl[t]      = g_poolL[g * 128 + t];
    pl[t + 64] = g_poolL[g * 128 + t + 64];
    pr[t]      = g_poolR[g * 128 + t];
    pr[t + 64] = g_poolR[g * 128 + t + 64];
    __syncthreads();
    float c = fmaxf(g_cnt[g], 1.0f);
    float acc = 0.f;
    const float4* wl4 = (const float4*)&Wl2[t * 128];
    const float4* wr4 = (const float4*)&Wr2[t * 128];
#pragma unroll 8
    for (int k4 = 0; k4 < 32; k4++) {
        float4 wl = __ldg(&wl4[k4]);
        float4 wr = __ldg(&wr4[k4]);
        int k = 4 * k4;
        acc += pl[k]     * wl.x + pl[k + 1] * wl.y + pl[k + 2] * wl.z + pl[k + 3] * wl.w;
        acc += pr[k]     * wr.x + pr[k + 1] * wr.y + pr[k + 2] * wr.z + pr[k + 3] * wr.w;
    }
    out[g * 64 + t] = acc / c + __ldg(&b2[t]);
}

// ---------------- launch ----------------
extern "C" void kernel_launch(void* const* d_in, const int* in_sizes, int n_in,
                              void* d_out, int out_size) {
    const float* x     = (const float*)d_in[0];
    const void*  ei    = d_in[1];
    const void*  batch = d_in[2];
    const float* Wl1   = (const float*)d_in[3];
    const float* Wr1   = (const float*)d_in[4];
    const float* b1    = (const float*)d_in[5];
    const float* Wl2   = (const float*)d_in[6];
    const float* Wr2   = (const float*)d_in[7];
    const float* b2    = (const float*)d_in[8];
    float* out = (float*)d_out;

    k_detect<<<1, 256>>>((const int*)ei);
    k_zero_small<<<512, 256>>>();
    k_transpose<<<64, 256>>>(Wl1, Wr1);

    // build CSR grouped by dst
    k_hist<<<2048, 256>>>(ei);
    k_scan<<<1, 1024>>>();
    k_fill<<<2048, 256>>>(ei);

    // layer 1: agg (gather-only) then fused gemm+relu
    k_agg1<<<(N_NODES * 32 + 255) / 256, 256>>>((const float4*)x);
    k_gemm1<<<(N_NODES + 31) / 32, 256>>>((const float4*)x, b1);

    // layer 2 aggregation fused with pooling
    k_agg2pool<<<(N_NODES * 32 + 255) / 256, 256>>>(batch);

    // tiny final GEMMs [256,128]x[128,64]
    k_final<<<N_GRAPHS, 64>>>(Wl2, Wr2, b2, out);
}

// round 6
// speedup vs baseline: 1.8326x; 1.3420x over previous
#include <cuda_runtime.h>
#include <cuda_fp16.h>
#include <cstdint>

#define N_NODES  100000
#define N_EDGES  3200000
#define N_GRAPHS 256
#define IN_DIM   128
#define HID_DIM  128
#define OUT_DIM  64

// ---------------- scratch (static device globals; no allocation) ----------------
__device__ __half g_xh  [(size_t)N_NODES * IN_DIM];   // 25.6 MB  x in fp16
__device__ __half g_agg1[(size_t)N_NODES * IN_DIM];   // 25.6 MB  layer-1 mean (fp16)
__device__ __half g_h   [(size_t)N_NODES * HID_DIM];  // 25.6 MB  hidden (fp16)
__device__ int   g_count [N_NODES];
__device__ int   g_rowptr[N_NODES + 1];
__device__ int   g_wcur  [N_NODES];
__device__ int   g_col   [N_EDGES];                   // CSR col = src, grouped by dst
__device__ float g_poolL[N_GRAPHS * HID_DIM];
__device__ float g_poolR[N_GRAPHS * HID_DIM];
__device__ float g_cnt [N_GRAPHS];
__device__ float g_WlT[IN_DIM * HID_DIM];             // WlT[k][o] = Wl1[o][k]
__device__ float g_WrT[IN_DIM * HID_DIM];
__device__ int   g_is64;

__device__ __forceinline__ int load_idx(const void* p, long long i, int is64) {
    if (is64) return (int)((const long long*)p)[i];
    return ((const int*)p)[i];
}

// ---------------- kernels ----------------

// Detect int64 vs int32 index buffers (JAX x64-disabled silently gives int32).
__global__ void k_detect(const int* __restrict__ ei32) {
    __shared__ int any_nonzero;
    if (threadIdx.x == 0) any_nonzero = 0;
    __syncthreads();
    for (int j = threadIdx.x; j < 2048; j += blockDim.x) {
        long long pos = 2LL * ((long long)j * 1553LL + 1) + 1;  // odd words
        if (pos < 2LL * N_EDGES * 2) {
            if (ei32[pos] != 0) atomicOr(&any_nonzero, 1);
        }
    }
    __syncthreads();
    if (threadIdx.x == 0) g_is64 = any_nonzero ? 0 : 1;
}

__global__ void k_zero_small() {
    int i = blockIdx.x * blockDim.x + threadIdx.x;
    int stride = gridDim.x * blockDim.x;
    for (int j = i; j < N_NODES; j += stride) g_count[j] = 0;
    for (int j = i; j < N_GRAPHS * HID_DIM; j += stride) { g_poolL[j] = 0.f; g_poolR[j] = 0.f; }
    if (i < N_GRAPHS) g_cnt[i] = 0.f;
}

__global__ void k_transpose(const float* __restrict__ Wl, const float* __restrict__ Wr) {
    int i = blockIdx.x * blockDim.x + threadIdx.x;
    if (i < IN_DIM * HID_DIM) {
        int o = i >> 7, k = i & 127;
        g_WlT[k * 128 + o] = Wl[i];
        g_WrT[k * 128 + o] = Wr[i];
    }
}

// x (fp32) -> g_xh (fp16), vectorized
__global__ void k_convert_x(const float4* __restrict__ x4) {
    int i = blockIdx.x * blockDim.x + threadIdx.x;
    int stride = gridDim.x * blockDim.x;
    uint2* dst = (uint2*)g_xh;
    const int total = N_NODES * IN_DIM / 4;   // 3.2M float4s
    for (int j = i; j < total; j += stride) {
        float4 v = __ldg(&x4[j]);
        __half2 h0 = __floats2half2_rn(v.x, v.y);
        __half2 h1 = __floats2half2_rn(v.z, v.w);
        uint2 u;
        u.x = *(unsigned*)&h0;
        u.y = *(unsigned*)&h1;
        dst[j] = u;
    }
}

// CSR build: histogram of dst
__global__ void k_hist(const void* __restrict__ ei) {
    const int is64 = g_is64;
    int i = blockIdx.x * blockDim.x + threadIdx.x;
    int stride = gridDim.x * blockDim.x;
    for (int e = i; e < N_EDGES; e += stride) {
        int d = load_idx(ei, (long long)N_EDGES + e, is64);
        d = min(max(d, 0), N_NODES - 1);
        atomicAdd(&g_count[d], 1);
    }
}

// CSR build: exclusive scan (single block)
__global__ void k_scan() {
    __shared__ int ssum[1024];
    int t = threadIdx.x;
    const int CH = (N_NODES + 1023) / 1024;   // 98
    int base = t * CH;
    int s = 0;
    for (int i = 0; i < CH; i++) {
        int n = base + i;
        if (n < N_NODES) s += g_count[n];
    }
    ssum[t] = s;
    __syncthreads();
    for (int off = 1; off < 1024; off <<= 1) {
        int v = (t >= off) ? ssum[t - off] : 0;
        __syncthreads();
        ssum[t] += v;
        __syncthreads();
    }
    int run = ssum[t] - s;
    for (int i = 0; i < CH; i++) {
        int n = base + i;
        if (n < N_NODES) {
            int c = g_count[n];
            g_rowptr[n] = run;
            g_wcur[n]   = run;
            run += c;
        }
    }
    if (t == 1023) g_rowptr[N_NODES] = run;
}

// CSR build: place src ids grouped by dst
__global__ void k_fill(const void* __restrict__ ei) {
    const int is64 = g_is64;
    int i = blockIdx.x * blockDim.x + threadIdx.x;
    int stride = gridDim.x * blockDim.x;
    for (int e = i; e < N_EDGES; e += stride) {
        int s = load_idx(ei, e, is64);
        int d = load_idx(ei, (long long)N_EDGES + e, is64);
        s = min(max(s, 0), N_NODES - 1);
        d = min(max(d, 0), N_NODES - 1);
        int pos = atomicAdd(&g_wcur[d], 1);
        g_col[pos] = s;
    }
}

// layer-1 aggregation (warp per node), fp16 gather -> fp32 accum -> fp16 mean
__global__ void k_agg1() {
    int lane = threadIdx.x & 31;
    int warp = (blockIdx.x * blockDim.x + threadIdx.x) >> 5;
    if (warp >= N_NODES) return;
    int n = warp;
    int beg = g_rowptr[n], end = g_rowptr[n + 1];
    float4 acc = make_float4(0.f, 0.f, 0.f, 0.f);
    const uint2* x2 = (const uint2*)g_xh;     // row = 32 x uint2 (4 halves each)
    for (int e0 = beg; e0 < end; e0 += 32) {
        int myc = (e0 + lane < end) ? g_col[e0 + lane] : 0;
        int m = min(32, end - e0);
        #pragma unroll 8
        for (int j = 0; j < m; j++) {
            int s = __shfl_sync(0xffffffff, myc, j);
            uint2 v = __ldg(&x2[(size_t)s * 32 + lane]);
            float2 f0 = __half22float2(*(__half2*)&v.x);
            float2 f1 = __half22float2(*(__half2*)&v.y);
            acc.x += f0.x; acc.y += f0.y; acc.z += f1.x; acc.w += f1.y;
        }
    }
    float r = 1.0f / fmaxf((float)(end - beg), 1.0f);
    __half2 o0 = __floats2half2_rn(acc.x * r, acc.y * r);
    __half2 o1 = __floats2half2_rn(acc.z * r, acc.w * r);
    uint2 u; u.x = *(unsigned*)&o0; u.y = *(unsigned*)&o1;
    ((uint2*)g_agg1)[(size_t)n * 32 + lane] = u;
}

// fused layer-1 GEMM: h = relu( agg1 @ Wl1^T + x @ Wr1^T + b1 ), fp16 in, fp16 out.
// 128 threads, 32 nodes/block; thread tile = 4 nodes x 8 outs.
__global__ void __launch_bounds__(128) k_gemm1(const float* __restrict__ b1) {
    __shared__ float4 sA4[32][33];   // [node][k4], fp32 after convert
    __shared__ float4 sX4[32][33];

    int tid = threadIdx.x;
    int n0 = blockIdx.x * 32;

    const uint2* a2 = (const uint2*)g_agg1;
    const uint2* x2 = (const uint2*)g_xh;
    for (int i = tid; i < 32 * 32; i += 128) {
        int n = i >> 5, k4 = i & 31;
        uint2 ua = __ldg(&a2[(size_t)(n0 + n) * 32 + k4]);
        uint2 ux = __ldg(&x2[(size_t)(n0 + n) * 32 + k4]);
        float2 a0 = __half22float2(*(__half2*)&ua.x);
        float2 a1 = __half22float2(*(__half2*)&ua.y);
        float2 f0 = __half22float2(*(__half2*)&ux.x);
        float2 f1 = __half22float2(*(__half2*)&ux.y);
        sA4[n][k4] = make_float4(a0.x, a0.y, a1.x, a1.y);
        sX4[n][k4] = make_float4(f0.x, f0.y, f1.x, f1.y);
    }
    __syncthreads();

    int og = tid & 15;   // outs 8*og .. 8*og+7
    int ng = tid >> 4;   // nodes 4*ng .. 4*ng+3

    float acc[4][8];
#pragma unroll
    for (int i = 0; i < 4; i++)
#pragma unroll
        for (int j = 0; j < 8; j++) acc[i][j] = 0.f;

    const float4* WlT4 = (const float4*)g_WlT;
    const float4* WrT4 = (const float4*)g_WrT;

    for (int k4 = 0; k4 < 32; k4++) {
        float4 av[4], xv[4];
#pragma unroll
        for (int i = 0; i < 4; i++) {
            av[i] = sA4[4 * ng + i][k4];
            xv[i] = sX4[4 * ng + i][k4];
        }
#pragma unroll
        for (int kk = 0; kk < 4; kk++) {
            int k = 4 * k4 + kk;
            float4 wl0 = __ldg(&WlT4[k * 32 + 2 * og]);
            float4 wl1 = __ldg(&WlT4[k * 32 + 2 * og + 1]);
            float4 wr0 = __ldg(&WrT4[k * 32 + 2 * og]);
            float4 wr1 = __ldg(&WrT4[k * 32 + 2 * og + 1]);
            float wl[8] = {wl0.x, wl0.y, wl0.z, wl0.w, wl1.x, wl1.y, wl1.z, wl1.w};
            float wr[8] = {wr0.x, wr0.y, wr0.z, wr0.w, wr1.x, wr1.y, wr1.z, wr1.w};
#pragma unroll
            for (int i = 0; i < 4; i++) {
                float a = ((const float*)&av[i])[kk];
                float xr = ((const float*)&xv[i])[kk];
#pragma unroll
                for (int j = 0; j < 8; j++)
                    acc[i][j] += a * wl[j] + xr * wr[j];
            }
        }
    }

    float bias[8];
#pragma unroll
    for (int j = 0; j < 8; j++) bias[j] = __ldg(&b1[8 * og + j]);

#pragma unroll
    for (int i = 0; i < 4; i++) {
        int n = n0 + 4 * ng + i;
        float o[8];
#pragma unroll
        for (int j = 0; j < 8; j++) o[j] = fmaxf(acc[i][j] + bias[j], 0.f);
        __half2 p0 = __floats2half2_rn(o[0], o[1]);
        __half2 p1 = __floats2half2_rn(o[2], o[3]);
        __half2 p2 = __floats2half2_rn(o[4], o[5]);
        __half2 p3 = __floats2half2_rn(o[6], o[7]);
        uint4 u;
        u.x = *(unsigned*)&p0; u.y = *(unsigned*)&p1;
        u.z = *(unsigned*)&p2; u.w = *(unsigned*)&p3;
        ((uint4*)g_h)[(size_t)n * 16 + og] = u;   // row = 128 halves = 16 uint4
    }
}

// layer-2 aggregation fused with pooling (warp per node), fp16 gather
__global__ void k_agg2pool(const void* __restrict__ batch) {
    const int is64 = g_is64;
    int lane = threadIdx.x & 31;
    int warp = (blockIdx.x * blockDim.x + threadIdx.x) >> 5;
    if (warp >= N_NODES) return;
    int n = warp;
    int beg = g_rowptr[n], end = g_rowptr[n + 1];
    float4 acc = make_float4(0.f, 0.f, 0.f, 0.f);
    const uint2* h2 = (const uint2*)g_h;
    for (int e0 = beg; e0 < end; e0 += 32) {
        int myc = (e0 + lane < end) ? g_col[e0 + lane] : 0;
        int m = min(32, end - e0);
        #pragma unroll 8
        for (int j = 0; j < m; j++) {
            int s = __shfl_sync(0xffffffff, myc, j);
            uint2 v = __ldg(&h2[(size_t)s * 32 + lane]);
            float2 f0 = __half22float2(*(__half2*)&v.x);
            float2 f1 = __half22float2(*(__half2*)&v.y);
            acc.x += f0.x; acc.y += f0.y; acc.z += f1.x; acc.w += f1.y;
        }
    }
    float r = 1.0f / fmaxf((float)(end - beg), 1.0f);
    acc.x *= r; acc.y *= r; acc.z *= r; acc.w *= r;

    int g = load_idx(batch, n, is64);
    g = min(max(g, 0), N_GRAPHS - 1);

    float4* pL = ((float4*)g_poolL) + g * 32 + lane;
    asm volatile("red.global.add.v4.f32 [%0], {%1,%2,%3,%4};"
                 :: "l"(pL), "f"(acc.x), "f"(acc.y), "f"(acc.z), "f"(acc.w) : "memory");

    uint2 hv = __ldg(&h2[(size_t)n * 32 + lane]);
    float2 f0 = __half22float2(*(__half2*)&hv.x);
    float2 f1 = __half22float2(*(__half2*)&hv.y);
    float4* pR = ((float4*)g_poolR) + g * 32 + lane;
    asm volatile("red.global.add.v4.f32 [%0], {%1,%2,%3,%4};"
                 :: "l"(pR), "f"(f0.x), "f"(f0.y), "f"(f1.x), "f"(f1.y) : "memory");
    if (lane == 0) atomicAdd(&g_cnt[g], 1.0f);
}

// final: out[g][o] = ( poolL[g]@Wl2[o]^T + poolR[g]@Wr2[o]^T ) / max(cnt,1) + b2[o]
__global__ void k_final(const float* __restrict__ Wl2, const float* __restrict__ Wr2,
                        const float* __restrict__ b2, float* __restrict__ out) {
    __shared__ float pl[128];
    __shared__ float pr[128];
    int g = blockIdx.x;
    int t = threadIdx.x;   // 64 threads
    pl[t]      = g_poolL[g * 128 + t];
    pl[t + 64] = g_poolL[g * 128 + t + 64];
    pr[t]      = g_poolR[g * 128 + t];
    pr[t + 64] = g_poolR[g * 128 + t + 64];
    __syncthreads();
    float c = fmaxf(g_cnt[g], 1.0f);
    float acc = 0.f;
    const float4* wl4 = (const float4*)&Wl2[t * 128];
    const float4* wr4 = (const float4*)&Wr2[t * 128];
#pragma unroll 8
    for (int k4 = 0; k4 < 32; k4++) {
        float4 wl = __ldg(&wl4[k4]);
        float4 wr = __ldg(&wr4[k4]);
        int k = 4 * k4;
        acc += pl[k]     * wl.x + pl[k + 1] * wl.y + pl[k + 2] * wl.z + pl[k + 3] * wl.w;
        acc += pr[k]     * wr.x + pr[k + 1] * wr.y + pr[k + 2] * wr.z + pr[k + 3] * wr.w;
    }
    out[g * 64 + t] = acc / c + __ldg(&b2[t]);
}

// ---------------- launch ----------------
extern "C" void kernel_launch(void* const* d_in, const int* in_sizes, int n_in,
                              void* d_out, int out_size) {
    const float* x     = (const float*)d_in[0];
    const void*  ei    = d_in[1];
    const void*  batch = d_in[2];
    const float* Wl1   = (const float*)d_in[3];
    const float* Wr1   = (const float*)d_in[4];
    const float* b1    = (const float*)d_in[5];
    const float* Wl2   = (const float*)d_in[6];
    const float* Wr2   = (const float*)d_in[7];
    const float* b2    = (const float*)d_in[8];
    float* out = (float*)d_out;

    k_detect<<<1, 256>>>((const int*)ei);
    k_zero_small<<<512, 256>>>();
    k_transpose<<<64, 256>>>(Wl1, Wr1);
    k_convert_x<<<2048, 256>>>((const float4*)x);

    // build CSR grouped by dst
    k_hist<<<2048, 256>>>(ei);
    k_scan<<<1, 1024>>>();
    k_fill<<<2048, 256>>>(ei);

    // layer 1: gather-mean then fused gemm+relu (fp16 operands)
    k_agg1<<<(N_NODES * 32 + 255) / 256, 256>>>();
    k_gemm1<<<N_NODES / 32, 128>>>(b1);

    // layer 2 aggregation fused with pooling
    k_agg2pool<<<(N_NODES * 32 + 255) / 256, 256>>>(batch);

    // tiny final GEMMs [256,128]x[128,64]
    k_final<<<N_GRAPHS, 64>>>(Wl2, Wr2, b2, out);
}

// round 7
// speedup vs baseline: 2.6301x; 1.4352x over previous
#include <cuda_runtime.h>
#include <cuda_fp16.h>
#include <cstdint>

#define N_NODES  100000
#define N_EDGES  3200000
#define N_GRAPHS 256
#define IN_DIM   128
#define HID_DIM  128
#define OUT_DIM  64

// ---------------- scratch (static device globals; no allocation) ----------------
__device__ __half g_xh  [(size_t)N_NODES * IN_DIM];   // 25.6 MB  x in fp16
__device__ __half g_agg1[(size_t)N_NODES * IN_DIM];   // 25.6 MB  layer-1 mean (fp16)
__device__ __half g_h   [(size_t)N_NODES * HID_DIM];  // 25.6 MB  hidden (fp16)
__device__ __half g_Wcat[HID_DIM * 256];              // [out][k] k = concat(Wl1, Wr1)
__device__ int   g_count [N_NODES];
__device__ int   g_rowptr[N_NODES + 1];
__device__ int   g_wcur  [N_NODES];
__device__ int   g_col   [N_EDGES];                   // CSR col = src, grouped by dst
__device__ float g_poolL[N_GRAPHS * HID_DIM];
__device__ float g_poolR[N_GRAPHS * HID_DIM];
__device__ float g_cnt [N_GRAPHS];
__device__ int   g_is64;

__device__ __forceinline__ int load_idx(const void* p, long long i, int is64) {
    if (is64) return (int)((const long long*)p)[i];
    return ((const int*)p)[i];
}

__device__ __forceinline__ void mma16816(float* c, const uint32_t* a, uint32_t b0, uint32_t b1) {
    asm volatile(
        "mma.sync.aligned.m16n8k16.row.col.f32.f16.f16.f32 "
        "{%0,%1,%2,%3}, {%4,%5,%6,%7}, {%8,%9}, {%0,%1,%2,%3};"
        : "+f"(c[0]), "+f"(c[1]), "+f"(c[2]), "+f"(c[3])
        : "r"(a[0]), "r"(a[1]), "r"(a[2]), "r"(a[3]), "r"(b0), "r"(b1));
}

// ---------------- kernels ----------------

// Detect int64 vs int32 index buffers (JAX x64-disabled silently gives int32).
__global__ void k_detect(const int* __restrict__ ei32) {
    __shared__ int any_nonzero;
    if (threadIdx.x == 0) any_nonzero = 0;
    __syncthreads();
    for (int j = threadIdx.x; j < 2048; j += blockDim.x) {
        long long pos = 2LL * ((long long)j * 1553LL + 1) + 1;  // odd words
        if (pos < 2LL * N_EDGES * 2) {
            if (ei32[pos] != 0) atomicOr(&any_nonzero, 1);
        }
    }
    __syncthreads();
    if (threadIdx.x == 0) g_is64 = any_nonzero ? 0 : 1;
}

__global__ void k_zero_small() {
    int i = blockIdx.x * blockDim.x + threadIdx.x;
    int stride = gridDim.x * blockDim.x;
    for (int j = i; j < N_NODES; j += stride) g_count[j] = 0;
    for (int j = i; j < N_GRAPHS * HID_DIM; j += stride) { g_poolL[j] = 0.f; g_poolR[j] = 0.f; }
    if (i < N_GRAPHS) g_cnt[i] = 0.f;
}

// build concatenated fp16 weight matrix Wcat[o][k], k<128 -> Wl1, k>=128 -> Wr1
__global__ void k_prepw(const float* __restrict__ Wl, const float* __restrict__ Wr) {
    int i = blockIdx.x * blockDim.x + threadIdx.x;   // 0 .. 32767
    if (i < HID_DIM * 256) {
        int o = i >> 8, k = i & 255;
        float v = (k < 128) ? Wl[o * 128 + k] : Wr[o * 128 + (k - 128)];
        g_Wcat[o * 256 + k] = __float2half_rn(v);
    }
}

// x (fp32) -> g_xh (fp16), vectorized
__global__ void k_convert_x(const float4* __restrict__ x4) {
    int i = blockIdx.x * blockDim.x + threadIdx.x;
    int stride = gridDim.x * blockDim.x;
    uint2* dst = (uint2*)g_xh;
    const int total = N_NODES * IN_DIM / 4;
    for (int j = i; j < total; j += stride) {
        float4 v = __ldg(&x4[j]);
        __half2 h0 = __floats2half2_rn(v.x, v.y);
        __half2 h1 = __floats2half2_rn(v.z, v.w);
        uint2 u;
        u.x = *(unsigned*)&h0;
        u.y = *(unsigned*)&h1;
        dst[j] = u;
    }
}

// CSR build: histogram of dst
__global__ void k_hist(const void* __restrict__ ei) {
    const int is64 = g_is64;
    int i = blockIdx.x * blockDim.x + threadIdx.x;
    int stride = gridDim.x * blockDim.x;
    for (int e = i; e < N_EDGES; e += stride) {
        int d = load_idx(ei, (long long)N_EDGES + e, is64);
        d = min(max(d, 0), N_NODES - 1);
        atomicAdd(&g_count[d], 1);
    }
}

// CSR build: exclusive scan (single block)
__global__ void k_scan() {
    __shared__ int ssum[1024];
    int t = threadIdx.x;
    const int CH = (N_NODES + 1023) / 1024;   // 98
    int base = t * CH;
    int s = 0;
    for (int i = 0; i < CH; i++) {
        int n = base + i;
        if (n < N_NODES) s += g_count[n];
    }
    ssum[t] = s;
    __syncthreads();
    for (int off = 1; off < 1024; off <<= 1) {
        int v = (t >= off) ? ssum[t - off] : 0;
        __syncthreads();
        ssum[t] += v;
        __syncthreads();
    }
    int run = ssum[t] - s;
    for (int i = 0; i < CH; i++) {
        int n = base + i;
        if (n < N_NODES) {
            int c = g_count[n];
            g_rowptr[n] = run;
            g_wcur[n]   = run;
            run += c;
        }
    }
    if (t == 1023) g_rowptr[N_NODES] = run;
}

// CSR build: place src ids grouped by dst
__global__ void k_fill(const void* __restrict__ ei) {
    const int is64 = g_is64;
    int i = blockIdx.x * blockDim.x + threadIdx.x;
    int stride = gridDim.x * blockDim.x;
    for (int e = i; e < N_EDGES; e += stride) {
        int s = load_idx(ei, e, is64);
        int d = load_idx(ei, (long long)N_EDGES + e, is64);
        s = min(max(s, 0), N_NODES - 1);
        d = min(max(d, 0), N_NODES - 1);
        int pos = atomicAdd(&g_wcur[d], 1);
        g_col[pos] = s;
    }
}

// layer-1 aggregation (warp per node), fp16 gather -> fp32 accum -> fp16 mean
__global__ void k_agg1() {
    int lane = threadIdx.x & 31;
    int warp = (blockIdx.x * blockDim.x + threadIdx.x) >> 5;
    if (warp >= N_NODES) return;
    int n = warp;
    int beg = g_rowptr[n], end = g_rowptr[n + 1];
    float4 acc = make_float4(0.f, 0.f, 0.f, 0.f);
    const uint2* x2 = (const uint2*)g_xh;     // row = 32 x uint2 (4 halves each)
    for (int e0 = beg; e0 < end; e0 += 32) {
        int myc = (e0 + lane < end) ? g_col[e0 + lane] : 0;
        int m = min(32, end - e0);
        #pragma unroll 8
        for (int j = 0; j < m; j++) {
            int s = __shfl_sync(0xffffffff, myc, j);
            uint2 v = __ldg(&x2[(size_t)s * 32 + lane]);
            float2 f0 = __half22float2(*(__half2*)&v.x);
            float2 f1 = __half22float2(*(__half2*)&v.y);
            acc.x += f0.x; acc.y += f0.y; acc.z += f1.x; acc.w += f1.y;
        }
    }
    float r = 1.0f / fmaxf((float)(end - beg), 1.0f);
    __half2 o0 = __floats2half2_rn(acc.x * r, acc.y * r);
    __half2 o1 = __floats2half2_rn(acc.z * r, acc.w * r);
    uint2 u; u.x = *(unsigned*)&o0; u.y = *(unsigned*)&o1;
    ((uint2*)g_agg1)[(size_t)n * 32 + lane] = u;
}

// layer-1 GEMM on tensor cores:
//   h = relu( concat(agg1, x) @ Wcat^T + b1 ),  all fp16 operands, fp32 accum.
// Block: 256 threads (8 warps). Tile: M=128 nodes x N=128 outs, K in 4 chunks of 64.
// Warp w handles rows 16w..16w+15; each warp covers all 16 n8 tiles.
__global__ void __launch_bounds__(256) k_gemm1_mma(const float* __restrict__ b1) {
    __shared__ __half sA[128][72];   // 64 data halves + 8 pad (stride 36 words: conflict-free)
    __shared__ __half sW[128][72];
    __shared__ float  sb[128];

    int tid = threadIdx.x;
    int lane = tid & 31;
    int w = tid >> 5;
    int n0 = blockIdx.x * 128;

    if (tid < 128) sb[tid] = __ldg(&b1[tid]);

    float acc[16][4];
#pragma unroll
    for (int t = 0; t < 16; t++)
#pragma unroll
        for (int j = 0; j < 4; j++) acc[t][j] = 0.f;

    const uint4* A1 = (const uint4*)g_agg1;   // 16 uint4 per 128-half row
    const uint4* AX = (const uint4*)g_xh;
    const uint4* WC = (const uint4*)g_Wcat;   // 32 uint4 per 256-half row

    for (int c = 0; c < 4; c++) {
        // stage A chunk (rows = nodes, k = 64c..64c+63) and W chunk
        for (int i = tid; i < 1024; i += 256) {
            int r = i >> 3, c8 = i & 7;
            int node = min(n0 + r, N_NODES - 1);
            uint4 va = (c < 2) ? __ldg(&A1[(size_t)node * 16 + c * 8 + c8])
                               : __ldg(&AX[(size_t)node * 16 + (c - 2) * 8 + c8]);
            *(uint4*)&sA[r][c8 * 8] = va;
            uint4 vw = __ldg(&WC[r * 32 + c * 8 + c8]);
            *(uint4*)&sW[r][c8 * 8] = vw;
        }
        __syncthreads();

#pragma unroll
        for (int ks = 0; ks < 4; ks++) {
            uint32_t a[4];
            int ar = w * 16 + (lane >> 2);
            int ah = ks * 16 + (lane & 3) * 2;   // half index within row
            a[0] = *(const uint32_t*)&sA[ar][ah];
            a[1] = *(const uint32_t*)&sA[ar + 8][ah];
            a[2] = *(const uint32_t*)&sA[ar][ah + 8];
            a[3] = *(const uint32_t*)&sA[ar + 8][ah + 8];
#pragma unroll
            for (int t = 0; t < 16; t++) {
                int br = t * 8 + (lane >> 2);
                uint32_t b0 = *(const uint32_t*)&sW[br][ah];
                uint32_t b1r = *(const uint32_t*)&sW[br][ah + 8];
                mma16816(acc[t], a, b0, b1r);
            }
        }
        __syncthreads();
    }

    // epilogue: bias + relu + fp16 pack + store
    int row = w * 16 + (lane >> 2);
    int node0 = n0 + row;
    int node1 = node0 + 8;
#pragma unroll
    for (int t = 0; t < 16; t++) {
        int col = t * 8 + (lane & 3) * 2;
        float b0f = sb[col], b1f = sb[col + 1];
        if (node0 < N_NODES) {
            __half2 p = __floats2half2_rn(fmaxf(acc[t][0] + b0f, 0.f),
                                          fmaxf(acc[t][1] + b1f, 0.f));
            *(uint32_t*)&g_h[(size_t)node0 * 128 + col] = *(uint32_t*)&p;
        }
        if (node1 < N_NODES) {
            __half2 p = __floats2half2_rn(fmaxf(acc[t][2] + b0f, 0.f),
                                          fmaxf(acc[t][3] + b1f, 0.f));
            *(uint32_t*)&g_h[(size_t)node1 * 128 + col] = *(uint32_t*)&p;
        }
    }
}

// layer-2 aggregation fused with pooling (warp per node), fp16 gather
__global__ void k_agg2pool(const void* __restrict__ batch) {
    const int is64 = g_is64;
    int lane = threadIdx.x & 31;
    int warp = (blockIdx.x * blockDim.x + threadIdx.x) >> 5;
    if (warp >= N_NODES) return;
    int n = warp;
    int beg = g_rowptr[n], end = g_rowptr[n + 1];
    float4 acc = make_float4(0.f, 0.f, 0.f, 0.f);
    const uint2* h2 = (const uint2*)g_h;
    for (int e0 = beg; e0 < end; e0 += 32) {
        int myc = (e0 + lane < end) ? g_col[e0 + lane] : 0;
        int m = min(32, end - e0);
        #pragma unroll 8
        for (int j = 0; j < m; j++) {
            int s = __shfl_sync(0xffffffff, myc, j);
            uint2 v = __ldg(&h2[(size_t)s * 32 + lane]);
            float2 f0 = __half22float2(*(__half2*)&v.x);
            float2 f1 = __half22float2(*(__half2*)&v.y);
            acc.x += f0.x; acc.y += f0.y; acc.z += f1.x; acc.w += f1.y;
        }
    }
    float r = 1.0f / fmaxf((float)(end - beg), 1.0f);
    acc.x *= r; acc.y *= r; acc.z *= r; acc.w *= r;

    int g = load_idx(batch, n, is64);
    g = min(max(g, 0), N_GRAPHS - 1);

    float4* pL = ((float4*)g_poolL) + g * 32 + lane;
    asm volatile("red.global.add.v4.f32 [%0], {%1,%2,%3,%4};"
                 :: "l"(pL), "f"(acc.x), "f"(acc.y), "f"(acc.z), "f"(acc.w) : "memory");

    uint2 hv = __ldg(&h2[(size_t)n * 32 + lane]);
    float2 f0 = __half22float2(*(__half2*)&hv.x);
    float2 f1 = __half22float2(*(__half2*)&hv.y);
    float4* pR = ((float4*)g_poolR) + g * 32 + lane;
    asm volatile("red.global.add.v4.f32 [%0], {%1,%2,%3,%4};"
                 :: "l"(pR), "f"(f0.x), "f"(f0.y), "f"(f1.x), "f"(f1.y) : "memory");
    if (lane == 0) atomicAdd(&g_cnt[g], 1.0f);
}

// final: out[g][o] = ( poolL[g]@Wl2[o]^T + poolR[g]@Wr2[o]^T ) / max(cnt,1) + b2[o]
__global__ void k_final(const float* __restrict__ Wl2, const float* __restrict__ Wr2,
                        const float* __restrict__ b2, float* __restrict__ out) {
    __shared__ float pl[128];
    __shared__ float pr[128];
    int g = blockIdx.x;
    int t = threadIdx.x;   // 64 threads
    pl[t]      = g_poolL[g * 128 + t];
    pl[t + 64] = g_poolL[g * 128 + t + 64];
    pr[t]      = g_poolR[g * 128 + t];
    pr[t + 64] = g_poolR[g * 128 + t + 64];
    __syncthreads();
    float c = fmaxf(g_cnt[g], 1.0f);
    float acc = 0.f;
    const float4* wl4 = (const float4*)&Wl2[t * 128];
    const float4* wr4 = (const float4*)&Wr2[t * 128];
#pragma unroll 8
    for (int k4 = 0; k4 < 32; k4++) {
        float4 wl = __ldg(&wl4[k4]);
        float4 wr = __ldg(&wr4[k4]);
        int k = 4 * k4;
        acc += pl[k]     * wl.x + pl[k + 1] * wl.y + pl[k + 2] * wl.z + pl[k + 3] * wl.w;
        acc += pr[k]     * wr.x + pr[k + 1] * wr.y + pr[k + 2] * wr.z + pr[k + 3] * wr.w;
    }
    out[g * 64 + t] = acc / c + __ldg(&b2[t]);
}

// ---------------- launch ----------------
extern "C" void kernel_launch(void* const* d_in, const int* in_sizes, int n_in,
                              void* d_out, int out_size) {
    const float* x     = (const float*)d_in[0];
    const void*  ei    = d_in[1];
    const void*  batch = d_in[2];
    const float* Wl1   = (const float*)d_in[3];
    const float* Wr1   = (const float*)d_in[4];
    const float* b1    = (const float*)d_in[5];
    const float* Wl2   = (const float*)d_in[6];
    const float* Wr2   = (const float*)d_in[7];
    const float* b2    = (const float*)d_in[8];
    float* out = (float*)d_out;

    k_detect<<<1, 256>>>((const int*)ei);
    k_zero_small<<<512, 256>>>();
    k_prepw<<<128, 256>>>(Wl1, Wr1);
    k_convert_x<<<2048, 256>>>((const float4*)x);

    // build CSR grouped by dst
    k_hist<<<2048, 256>>>(ei);
    k_scan<<<1, 1024>>>();
    k_fill<<<2048, 256>>>(ei);

    // layer 1: gather-mean then tensor-core gemm+relu
    k_agg1<<<(N_NODES * 32 + 255) / 256, 256>>>();
    k_gemm1_mma<<<(N_NODES + 127) / 128, 256>>>(b1);

    // layer 2 aggregation fused with pooling
    k_agg2pool<<<(N_NODES * 32 + 255) / 256, 256>>>(batch);

    // tiny final GEMMs [256,128]x[128,64]
    k_final<<<N_GRAPHS, 64>>>(Wl2, Wr2, b2, out);
}

// round 8
// speedup vs baseline: 3.3038x; 1.2562x over previous
#include <cuda_runtime.h>
#include <cuda_fp16.h>
#include <cstdint>

#define N_NODES  100000
#define N_EDGES  3200000
#define N_GRAPHS 256
#define IN_DIM   128
#define HID_DIM  128
#define OUT_DIM  64

// ---------------- scratch (static device globals; no allocation) ----------------
__device__ __half g_xh  [(size_t)N_NODES * IN_DIM];   // 25.6 MB  x in fp16
__device__ __half g_agg1[(size_t)N_NODES * IN_DIM];   // 25.6 MB  layer-1 mean (fp16)
__device__ __half g_h   [(size_t)N_NODES * HID_DIM];  // 25.6 MB  hidden (fp16)
__device__ __half g_Wcat[HID_DIM * 256];              // [out][k] k = concat(Wl1, Wr1)
__device__ int   g_count [N_NODES];
__device__ int   g_rowptr[N_NODES + 1];
__device__ int   g_wcur  [N_NODES];
__device__ int   g_col   [N_EDGES];                   // CSR col = src, grouped by dst
__device__ int   g_bsum[128];
__device__ int   g_boff[128];
__device__ float g_poolL[N_GRAPHS * HID_DIM];
__device__ float g_poolR[N_GRAPHS * HID_DIM];
__device__ float g_cnt [N_GRAPHS];
__device__ int   g_is64;

__device__ __forceinline__ int load_idx(const void* p, long long i, int is64) {
    if (is64) return (int)((const long long*)p)[i];
    return ((const int*)p)[i];
}

__device__ __forceinline__ void mma16816(float* c, const uint32_t* a, uint32_t b0, uint32_t b1) {
    asm volatile(
        "mma.sync.aligned.m16n8k16.row.col.f32.f16.f16.f32 "
        "{%0,%1,%2,%3}, {%4,%5,%6,%7}, {%8,%9}, {%0,%1,%2,%3};"
        : "+f"(c[0]), "+f"(c[1]), "+f"(c[2]), "+f"(c[3])
        : "r"(a[0]), "r"(a[1]), "r"(a[2]), "r"(a[3]), "r"(b0), "r"(b1));
}

// ---------------- kernels ----------------

// setup: zero counters/pools, build fp16 Wcat, detect index dtype (block 0).
__global__ void k_setup(const int* __restrict__ ei32,
                        const float* __restrict__ Wl, const float* __restrict__ Wr) {
    int i = blockIdx.x * blockDim.x + threadIdx.x;
    int stride = gridDim.x * blockDim.x;
    for (int j = i; j < N_NODES; j += stride) g_count[j] = 0;
    for (int j = i; j < N_GRAPHS * HID_DIM; j += stride) { g_poolL[j] = 0.f; g_poolR[j] = 0.f; }
    if (i < N_GRAPHS) g_cnt[i] = 0.f;
    for (int j = i; j < HID_DIM * 256; j += stride) {
        int o = j >> 8, k = j & 255;
        float v = (k < 128) ? Wl[o * 128 + k] : Wr[o * 128 + (k - 128)];
        g_Wcat[o * 256 + k] = __float2half_rn(v);
    }
    if (blockIdx.x == 0) {
        __shared__ int any_nonzero;
        if (threadIdx.x == 0) any_nonzero = 0;
        __syncthreads();
        for (int j = threadIdx.x; j < 2048; j += blockDim.x) {
            long long pos = 2LL * ((long long)j * 1553LL + 1) + 1;  // odd words, max < 2*N_EDGES
            if (pos < 2LL * N_EDGES) {
                if (ei32[pos] != 0) atomicOr(&any_nonzero, 1);
            }
        }
        __syncthreads();
        if (threadIdx.x == 0) g_is64 = any_nonzero ? 0 : 1;
    }
}

// x (fp32) -> g_xh (fp16), vectorized
__global__ void k_convert_x(const float4* __restrict__ x4) {
    int i = blockIdx.x * blockDim.x + threadIdx.x;
    int stride = gridDim.x * blockDim.x;
    uint2* dst = (uint2*)g_xh;
    const int total = N_NODES * IN_DIM / 4;
    for (int j = i; j < total; j += stride) {
        float4 v = __ldg(&x4[j]);
        __half2 h0 = __floats2half2_rn(v.x, v.y);
        __half2 h1 = __floats2half2_rn(v.z, v.w);
        uint2 u;
        u.x = *(unsigned*)&h0;
        u.y = *(unsigned*)&h1;
        dst[j] = u;
    }
}

// CSR build: histogram of dst
__global__ void k_hist(const void* __restrict__ ei) {
    const int is64 = g_is64;
    int i = blockIdx.x * blockDim.x + threadIdx.x;
    int stride = gridDim.x * blockDim.x;
    for (int e = i; e < N_EDGES; e += stride) {
        int d = load_idx(ei, (long long)N_EDGES + e, is64);
        d = min(max(d, 0), N_NODES - 1);
        atomicAdd(&g_count[d], 1);
    }
}

// scan phase 1: per-block (1024-elem) exclusive scan, coalesced
__global__ void k_scan1() {
    __shared__ int sh[1024];
    int t = threadIdx.x;
    int n = blockIdx.x * 1024 + t;
    int v = (n < N_NODES) ? g_count[n] : 0;
    sh[t] = v;
    __syncthreads();
    for (int off = 1; off < 1024; off <<= 1) {
        int u = (t >= off) ? sh[t - off] : 0;
        __syncthreads();
        sh[t] += u;
        __syncthreads();
    }
    if (n < N_NODES) g_rowptr[n] = sh[t] - v;   // exclusive within block
    if (t == 1023) g_bsum[blockIdx.x] = sh[1023];
}

// scan phase 2: scan the 98 block sums
__global__ void k_scan2() {
    __shared__ int sh[128];
    int t = threadIdx.x;
    const int NB = (N_NODES + 1023) / 1024;   // 98
    int v = (t < NB) ? g_bsum[t] : 0;
    sh[t] = v;
    __syncthreads();
    for (int off = 1; off < 128; off <<= 1) {
        int u = (t >= off) ? sh[t - off] : 0;
        __syncthreads();
        sh[t] += u;
        __syncthreads();
    }
    if (t < NB) g_boff[t] = sh[t] - v;
}

// scan phase 3: apply block offsets, init write cursors
__global__ void k_scan3() {
    int i = blockIdx.x * blockDim.x + threadIdx.x;
    if (i < N_NODES) {
        int r = g_rowptr[i] + g_boff[i >> 10];
        g_rowptr[i] = r;
        g_wcur[i] = r;
    }
    if (i == 0) g_rowptr[N_NODES] = N_EDGES;
}

// CSR build: place src ids grouped by dst
__global__ void k_fill(const void* __restrict__ ei) {
    const int is64 = g_is64;
    int i = blockIdx.x * blockDim.x + threadIdx.x;
    int stride = gridDim.x * blockDim.x;
    for (int e = i; e < N_EDGES; e += stride) {
        int s = load_idx(ei, e, is64);
        int d = load_idx(ei, (long long)N_EDGES + e, is64);
        s = min(max(s, 0), N_NODES - 1);
        d = min(max(d, 0), N_NODES - 1);
        int pos = atomicAdd(&g_wcur[d], 1);
        g_col[pos] = s;
    }
}

// layer-1 aggregation (warp per node), 2 edges per warp-iter via uint4:
// lanes 0-15 handle even edges, lanes 16-31 odd edges; cross-half reduce at end.
__global__ void k_agg1() {
    int lane = threadIdx.x & 31;
    int n = (blockIdx.x * blockDim.x + threadIdx.x) >> 5;
    if (n >= N_NODES) return;
    int beg = g_rowptr[n], end = g_rowptr[n + 1];
    int half = lane >> 4, l16 = lane & 15;
    float acc[8] = {0.f, 0.f, 0.f, 0.f, 0.f, 0.f, 0.f, 0.f};
    const uint4* x4 = (const uint4*)g_xh;     // row = 16 uint4 (8 halves each)
    for (int e0 = beg; e0 < end; e0 += 32) {
        int myc = (e0 + lane < end) ? g_col[e0 + lane] : -1;
        int m = min(32, end - e0);
        int npair = (m + 1) >> 1;
        for (int j = 0; j < npair; j++) {
            int s0 = __shfl_sync(0xffffffff, myc, 2 * j);
            int s1 = __shfl_sync(0xffffffff, myc, 2 * j + 1);
            int s = half ? s1 : s0;
            if (s >= 0) {
                uint4 v = __ldg(&x4[(size_t)s * 16 + l16]);
                float2 f0 = __half22float2(*(__half2*)&v.x);
                float2 f1 = __half22float2(*(__half2*)&v.y);
                float2 f2 = __half22float2(*(__half2*)&v.z);
                float2 f3 = __half22float2(*(__half2*)&v.w);
                acc[0] += f0.x; acc[1] += f0.y; acc[2] += f1.x; acc[3] += f1.y;
                acc[4] += f2.x; acc[5] += f2.y; acc[6] += f3.x; acc[7] += f3.y;
            }
        }
    }
#pragma unroll
    for (int c = 0; c < 8; c++) acc[c] += __shfl_xor_sync(0xffffffff, acc[c], 16);
    if (half == 0) {
        float r = 1.0f / fmaxf((float)(end - beg), 1.0f);
        __half2 p0 = __floats2half2_rn(acc[0] * r, acc[1] * r);
        __half2 p1 = __floats2half2_rn(acc[2] * r, acc[3] * r);
        __half2 p2 = __floats2half2_rn(acc[4] * r, acc[5] * r);
        __half2 p3 = __floats2half2_rn(acc[6] * r, acc[7] * r);
        uint4 u;
        u.x = *(unsigned*)&p0; u.y = *(unsigned*)&p1;
        u.z = *(unsigned*)&p2; u.w = *(unsigned*)&p3;
        ((uint4*)g_agg1)[(size_t)n * 16 + l16] = u;
    }
}

// layer-1 GEMM on tensor cores:
//   h = relu( concat(agg1, x) @ Wcat^T + b1 ),  fp16 operands, fp32 accum.
__global__ void __launch_bounds__(256) k_gemm1_mma(const float* __restrict__ b1) {
    __shared__ __half sA[128][72];   // 64 data halves + 8 pad
    __shared__ __half sW[128][72];
    __shared__ float  sb[128];

    int tid = threadIdx.x;
    int lane = tid & 31;
    int w = tid >> 5;
    int n0 = blockIdx.x * 128;

    if (tid < 128) sb[tid] = __ldg(&b1[tid]);

    float acc[16][4];
#pragma unroll
    for (int t = 0; t < 16; t++)
#pragma unroll
        for (int j = 0; j < 4; j++) acc[t][j] = 0.f;

    const uint4* A1 = (const uint4*)g_agg1;
    const uint4* AX = (const uint4*)g_xh;
    const uint4* WC = (const uint4*)g_Wcat;

    for (int c = 0; c < 4; c++) {
        for (int i = tid; i < 1024; i += 256) {
            int r = i >> 3, c8 = i & 7;
            int node = min(n0 + r, N_NODES - 1);
            uint4 va = (c < 2) ? __ldg(&A1[(size_t)node * 16 + c * 8 + c8])
                               : __ldg(&AX[(size_t)node * 16 + (c - 2) * 8 + c8]);
            *(uint4*)&sA[r][c8 * 8] = va;
            uint4 vw = __ldg(&WC[r * 32 + c * 8 + c8]);
            *(uint4*)&sW[r][c8 * 8] = vw;
        }
        __syncthreads();

#pragma unroll
        for (int ks = 0; ks < 4; ks++) {
            uint32_t a[4];
            int ar = w * 16 + (lane >> 2);
            int ah = ks * 16 + (lane & 3) * 2;
            a[0] = *(const uint32_t*)&sA[ar][ah];
            a[1] = *(const uint32_t*)&sA[ar + 8][ah];
            a[2] = *(const uint32_t*)&sA[ar][ah + 8];
            a[3] = *(const uint32_t*)&sA[ar + 8][ah + 8];
#pragma unroll
            for (int t = 0; t < 16; t++) {
                int br = t * 8 + (lane >> 2);
                uint32_t b0 = *(const uint32_t*)&sW[br][ah];
                uint32_t b1r = *(const uint32_t*)&sW[br][ah + 8];
                mma16816(acc[t], a, b0, b1r);
            }
        }
        __syncthreads();
    }

    int row = w * 16 + (lane >> 2);
    int node0 = n0 + row;
    int node1 = node0 + 8;
#pragma unroll
    for (int t = 0; t < 16; t++) {
        int col = t * 8 + (lane & 3) * 2;
        float b0f = sb[col], b1f = sb[col + 1];
        if (node0 < N_NODES) {
            __half2 p = __floats2half2_rn(fmaxf(acc[t][0] + b0f, 0.f),
                                          fmaxf(acc[t][1] + b1f, 0.f));
            *(uint32_t*)&g_h[(size_t)node0 * 128 + col] = *(uint32_t*)&p;
        }
        if (node1 < N_NODES) {
            __half2 p = __floats2half2_rn(fmaxf(acc[t][2] + b0f, 0.f),
                                          fmaxf(acc[t][3] + b1f, 0.f));
            *(uint32_t*)&g_h[(size_t)node1 * 128 + col] = *(uint32_t*)&p;
        }
    }
}

// layer-2 aggregation fused with pooling (warp per node), 2-edge uint4 gather
__global__ void k_agg2pool(const void* __restrict__ batch) {
    const int is64 = g_is64;
    int lane = threadIdx.x & 31;
    int n = (blockIdx.x * blockDim.x + threadIdx.x) >> 5;
    if (n >= N_NODES) return;
    int beg = g_rowptr[n], end = g_rowptr[n + 1];
    int half = lane >> 4, l16 = lane & 15;
    float acc[8] = {0.f, 0.f, 0.f, 0.f, 0.f, 0.f, 0.f, 0.f};
    const uint4* h4 = (const uint4*)g_h;
    for (int e0 = beg; e0 < end; e0 += 32) {
        int myc = (e0 + lane < end) ? g_col[e0 + lane] : -1;
        int m = min(32, end - e0);
        int npair = (m + 1) >> 1;
        for (int j = 0; j < npair; j++) {
            int s0 = __shfl_sync(0xffffffff, myc, 2 * j);
            int s1 = __shfl_sync(0xffffffff, myc, 2 * j + 1);
            int s = half ? s1 : s0;
            if (s >= 0) {
                uint4 v = __ldg(&h4[(size_t)s * 16 + l16]);
                float2 f0 = __half22float2(*(__half2*)&v.x);
                float2 f1 = __half22float2(*(__half2*)&v.y);
                float2 f2 = __half22float2(*(__half2*)&v.z);
                float2 f3 = __half22float2(*(__half2*)&v.w);
                acc[0] += f0.x; acc[1] += f0.y; acc[2] += f1.x; acc[3] += f1.y;
                acc[4] += f2.x; acc[5] += f2.y; acc[6] += f3.x; acc[7] += f3.y;
            }
        }
    }
#pragma unroll
    for (int c = 0; c < 8; c++) acc[c] += __shfl_xor_sync(0xffffffff, acc[c], 16);

    int g = load_idx(batch, n, is64);
    g = min(max(g, 0), N_GRAPHS - 1);

    if (half == 0) {
        float r = 1.0f / fmaxf((float)(end - beg), 1.0f);
        float* pL = g_poolL + g * 128 + l16 * 8;
        asm volatile("red.global.add.v4.f32 [%0], {%1,%2,%3,%4};"
                     :: "l"(pL), "f"(acc[0] * r), "f"(acc[1] * r), "f"(acc[2] * r), "f"(acc[3] * r) : "memory");
        asm volatile("red.global.add.v4.f32 [%0], {%1,%2,%3,%4};"
                     :: "l"(pL + 4), "f"(acc[4] * r), "f"(acc[5] * r), "f"(acc[6] * r), "f"(acc[7] * r) : "memory");

        uint4 hv = __ldg(&h4[(size_t)n * 16 + l16]);
        float2 f0 = __half22float2(*(__half2*)&hv.x);
        float2 f1 = __half22float2(*(__half2*)&hv.y);
        float2 f2 = __half22float2(*(__half2*)&hv.z);
        float2 f3 = __half22float2(*(__half2*)&hv.w);
        float* pR = g_poolR + g * 128 + l16 * 8;
        asm volatile("red.global.add.v4.f32 [%0], {%1,%2,%3,%4};"
                     :: "l"(pR), "f"(f0.x), "f"(f0.y), "f"(f1.x), "f"(f1.y) : "memory");
        asm volatile("red.global.add.v4.f32 [%0], {%1,%2,%3,%4};"
                     :: "l"(pR + 4), "f"(f2.x), "f"(f2.y), "f"(f3.x), "f"(f3.y) : "memory");
        if (lane == 0) atomicAdd(&g_cnt[g], 1.0f);
    }
}

// final: out[g][o] = ( poolL[g]@Wl2[o]^T + poolR[g]@Wr2[o]^T ) / max(cnt,1) + b2[o]
__global__ void k_final(const float* __restrict__ Wl2, const float* __restrict__ Wr2,
                        const float* __restrict__ b2, float* __restrict__ out) {
    __shared__ float pl[128];
    __shared__ float pr[128];
    int g = blockIdx.x;
    int t = threadIdx.x;   // 64 threads
    pl[t]      = g_poolL[g * 128 + t];
    pl[t + 64] = g_poolL[g * 128 + t + 64];
    pr[t]      = g_poolR[g * 128 + t];
    pr[t + 64] = g_poolR[g * 128 + t + 64];
    __syncthreads();
    float c = fmaxf(g_cnt[g], 1.0f);
    float acc = 0.f;
    const float4* wl4 = (const float4*)&Wl2[t * 128];
    const float4* wr4 = (const float4*)&Wr2[t * 128];
#pragma unroll 8
    for (int k4 = 0; k4 < 32; k4++) {
        float4 wl = __ldg(&wl4[k4]);
        float4 wr = __ldg(&wr4[k4]);
        int k = 4 * k4;
        acc += pl[k]     * wl.x + pl[k + 1] * wl.y + pl[k + 2] * wl.z + pl[k + 3] * wl.w;
        acc += pr[k]     * wr.x + pr[k + 1] * wr.y + pr[k + 2] * wr.z + pr[k + 3] * wr.w;
    }
    out[g * 64 + t] = acc / c + __ldg(&b2[t]);
}

// ---------------- launch ----------------
extern "C" void kernel_launch(void* const* d_in, const int* in_sizes, int n_in,
                              void* d_out, int out_size) {
    const float* x     = (const float*)d_in[0];
    const void*  ei    = d_in[1];
    const void*  batch = d_in[2];
    const float* Wl1   = (const float*)d_in[3];
    const float* Wr1   = (const float*)d_in[4];
    const float* b1    = (const float*)d_in[5];
    const float* Wl2   = (const float*)d_in[6];
    const float* Wr2   = (const float*)d_in[7];
    const float* b2    = (const float*)d_in[8];
    float* out = (float*)d_out;

    k_setup<<<512, 256>>>((const int*)ei, Wl1, Wr1);
    k_convert_x<<<2048, 256>>>((const float4*)x);

    // build CSR grouped by dst
    k_hist<<<2048, 256>>>(ei);
    k_scan1<<<(N_NODES + 1023) / 1024, 1024>>>();
    k_scan2<<<1, 128>>>();
    k_scan3<<<(N_NODES + 255) / 256, 256>>>();
    k_fill<<<2048, 256>>>(ei);

    // layer 1: gather-mean then tensor-core gemm+relu
    k_agg1<<<(N_NODES * 32 + 255) / 256, 256>>>();
    k_gemm1_mma<<<(N_NODES + 127) / 128, 256>>>(b1);

    // layer 2 aggregation fused with pooling
    k_agg2pool<<<(N_NODES * 32 + 255) / 256, 256>>>(batch);

    // tiny final GEMMs [256,128]x[128,64]
    k_final<<<N_GRAPHS, 64>>>(Wl2, Wr2, b2, out);
}

// round 9
// speedup vs baseline: 3.3560x; 1.0158x over previous
#include <cuda_runtime.h>
#include <cuda_fp16.h>
#include <cstdint>

#define N_NODES  100000
#define N_EDGES  3200000
#define N_GRAPHS 256
#define IN_DIM   128
#define HID_DIM  128
#define OUT_DIM  64

// ---------------- scratch (static device globals; no allocation) ----------------
__device__ __half g_xh  [(size_t)N_NODES * IN_DIM];   // 25.6 MB  x in fp16
__device__ __half g_agg1[(size_t)N_NODES * IN_DIM];   // 25.6 MB  layer-1 mean (fp16)
__device__ __half g_h   [(size_t)N_NODES * HID_DIM];  // 25.6 MB  hidden (fp16)
__device__ __half g_Wcat[HID_DIM * 256];              // [out][k] k = concat(Wl1, Wr1)
__device__ int   g_count [N_NODES];
__device__ int   g_rowptr[N_NODES + 1];
__device__ int   g_wcur  [N_NODES];
__device__ int   g_col   [N_EDGES];                   // CSR col = src, grouped by dst
__device__ int   g_bsum[128];
__device__ int   g_boff[128];
__device__ float g_poolL[N_GRAPHS * HID_DIM];
__device__ float g_poolR[N_GRAPHS * HID_DIM];
__device__ float g_cnt [N_GRAPHS];
__device__ int   g_is64;

__device__ __forceinline__ void mma16816(float* c, const uint32_t* a, uint32_t b0, uint32_t b1) {
    asm volatile(
        "mma.sync.aligned.m16n8k16.row.col.f32.f16.f16.f32 "
        "{%0,%1,%2,%3}, {%4,%5,%6,%7}, {%8,%9}, {%0,%1,%2,%3};"
        : "+f"(c[0]), "+f"(c[1]), "+f"(c[2]), "+f"(c[3])
        : "r"(a[0]), "r"(a[1]), "r"(a[2]), "r"(a[3]), "r"(b0), "r"(b1));
}

// ---------------- kernels ----------------

// setup: zero counters/pools, build fp16 Wcat, convert x -> fp16, detect dtype (block 0).
__global__ void k_setup(const int* __restrict__ ei32,
                        const float* __restrict__ Wl, const float* __restrict__ Wr,
                        const float4* __restrict__ x4) {
    int i = blockIdx.x * blockDim.x + threadIdx.x;
    int stride = gridDim.x * blockDim.x;
    for (int j = i; j < N_NODES; j += stride) g_count[j] = 0;
    for (int j = i; j < N_GRAPHS * HID_DIM; j += stride) { g_poolL[j] = 0.f; g_poolR[j] = 0.f; }
    if (i < N_GRAPHS) g_cnt[i] = 0.f;
    for (int j = i; j < HID_DIM * 256; j += stride) {
        int o = j >> 8, k = j & 255;
        float v = (k < 128) ? Wl[o * 128 + k] : Wr[o * 128 + (k - 128)];
        g_Wcat[o * 256 + k] = __float2half_rn(v);
    }
    // x fp32 -> fp16
    {
        uint2* dst = (uint2*)g_xh;
        const int total = N_NODES * IN_DIM / 4;
        for (int j = i; j < total; j += stride) {
            float4 v = __ldg(&x4[j]);
            __half2 h0 = __floats2half2_rn(v.x, v.y);
            __half2 h1 = __floats2half2_rn(v.z, v.w);
            uint2 u;
            u.x = *(unsigned*)&h0;
            u.y = *(unsigned*)&h1;
            dst[j] = u;
        }
    }
    if (blockIdx.x == 0) {
        __shared__ int any_nonzero;
        if (threadIdx.x == 0) any_nonzero = 0;
        __syncthreads();
        for (int j = threadIdx.x; j < 2048; j += blockDim.x) {
            long long pos = 2LL * ((long long)j * 1553LL + 1) + 1;  // odd words
            if (pos < 2LL * N_EDGES) {
                if (ei32[pos] != 0) atomicOr(&any_nonzero, 1);
            }
        }
        __syncthreads();
        if (threadIdx.x == 0) g_is64 = any_nonzero ? 0 : 1;
    }
}

// CSR build: histogram of dst (2 edges per thread, vector loads)
__global__ void k_hist(const void* __restrict__ ei) {
    const int is64 = g_is64;
    int i = blockIdx.x * blockDim.x + threadIdx.x;
    int stride = gridDim.x * blockDim.x;
    const int E2 = N_EDGES / 2;
    if (is64) {
        const longlong2* d2 = (const longlong2*)((const long long*)ei + N_EDGES);
        for (int e = i; e < E2; e += stride) {
            longlong2 v = __ldg(&d2[e]);
            int d0 = min(max((int)v.x, 0), N_NODES - 1);
            int d1 = min(max((int)v.y, 0), N_NODES - 1);
            atomicAdd(&g_count[d0], 1);
            atomicAdd(&g_count[d1], 1);
        }
    } else {
        const int2* d2 = (const int2*)((const int*)ei + N_EDGES);
        for (int e = i; e < E2; e += stride) {
            int2 v = __ldg(&d2[e]);
            int d0 = min(max(v.x, 0), N_NODES - 1);
            int d1 = min(max(v.y, 0), N_NODES - 1);
            atomicAdd(&g_count[d0], 1);
            atomicAdd(&g_count[d1], 1);
        }
    }
}

// scan phase 1: per-block (1024-elem) exclusive scan, coalesced
__global__ void k_scan1() {
    __shared__ int sh[1024];
    int t = threadIdx.x;
    int n = blockIdx.x * 1024 + t;
    int v = (n < N_NODES) ? g_count[n] : 0;
    sh[t] = v;
    __syncthreads();
    for (int off = 1; off < 1024; off <<= 1) {
        int u = (t >= off) ? sh[t - off] : 0;
        __syncthreads();
        sh[t] += u;
        __syncthreads();
    }
    if (n < N_NODES) g_rowptr[n] = sh[t] - v;   // exclusive within block
    if (t == 1023) g_bsum[blockIdx.x] = sh[1023];
}

// scan phase 2: scan the 98 block sums
__global__ void k_scan2() {
    __shared__ int sh[128];
    int t = threadIdx.x;
    const int NB = (N_NODES + 1023) / 1024;   // 98
    int v = (t < NB) ? g_bsum[t] : 0;
    sh[t] = v;
    __syncthreads();
    for (int off = 1; off < 128; off <<= 1) {
        int u = (t >= off) ? sh[t - off] : 0;
        __syncthreads();
        sh[t] += u;
        __syncthreads();
    }
    if (t < NB) g_boff[t] = sh[t] - v;
}

// scan phase 3: apply block offsets, init write cursors
__global__ void k_scan3() {
    int i = blockIdx.x * blockDim.x + threadIdx.x;
    if (i < N_NODES) {
        int r = g_rowptr[i] + g_boff[i >> 10];
        g_rowptr[i] = r;
        g_wcur[i] = r;
    }
    if (i == 0) g_rowptr[N_NODES] = N_EDGES;
}

// CSR build: place src ids grouped by dst (2 edges per thread, vector loads)
__global__ void k_fill(const void* __restrict__ ei) {
    const int is64 = g_is64;
    int i = blockIdx.x * blockDim.x + threadIdx.x;
    int stride = gridDim.x * blockDim.x;
    const int E2 = N_EDGES / 2;
    if (is64) {
        const longlong2* s2 = (const longlong2*)ei;
        const longlong2* d2 = (const longlong2*)((const long long*)ei + N_EDGES);
        for (int e = i; e < E2; e += stride) {
            longlong2 sv = __ldg(&s2[e]);
            longlong2 dv = __ldg(&d2[e]);
            int s0 = min(max((int)sv.x, 0), N_NODES - 1);
            int s1 = min(max((int)sv.y, 0), N_NODES - 1);
            int d0 = min(max((int)dv.x, 0), N_NODES - 1);
            int d1 = min(max((int)dv.y, 0), N_NODES - 1);
            g_col[atomicAdd(&g_wcur[d0], 1)] = s0;
            g_col[atomicAdd(&g_wcur[d1], 1)] = s1;
        }
    } else {
        const int2* s2 = (const int2*)ei;
        const int2* d2 = (const int2*)((const int*)ei + N_EDGES);
        for (int e = i; e < E2; e += stride) {
            int2 sv = __ldg(&s2[e]);
            int2 dv = __ldg(&d2[e]);
            int s0 = min(max(sv.x, 0), N_NODES - 1);
            int s1 = min(max(sv.y, 0), N_NODES - 1);
            int d0 = min(max(dv.x, 0), N_NODES - 1);
            int d1 = min(max(dv.y, 0), N_NODES - 1);
            g_col[atomicAdd(&g_wcur[d0], 1)] = s0;
            g_col[atomicAdd(&g_wcur[d1], 1)] = s1;
        }
    }
}

// layer-1 aggregation (warp per node), 2 edges per warp-iter via uint4:
// lanes 0-15 handle even edges, lanes 16-31 odd edges; cross-half reduce at end.
__global__ void k_agg1() {
    int lane = threadIdx.x & 31;
    int n = (blockIdx.x * blockDim.x + threadIdx.x) >> 5;
    if (n >= N_NODES) return;
    int beg = g_rowptr[n], end = g_rowptr[n + 1];
    int half = lane >> 4, l16 = lane & 15;
    float acc[8] = {0.f, 0.f, 0.f, 0.f, 0.f, 0.f, 0.f, 0.f};
    const uint4* x4 = (const uint4*)g_xh;     // row = 16 uint4 (8 halves each)
    for (int e0 = beg; e0 < end; e0 += 32) {
        int myc = (e0 + lane < end) ? g_col[e0 + lane] : -1;
        int m = min(32, end - e0);
        int npair = (m + 1) >> 1;
        for (int j = 0; j < npair; j++) {
            int s0 = __shfl_sync(0xffffffff, myc, 2 * j);
            int s1 = __shfl_sync(0xffffffff, myc, 2 * j + 1);
            int s = half ? s1 : s0;
            if (s >= 0) {
                uint4 v = __ldg(&x4[(size_t)s * 16 + l16]);
                float2 f0 = __half22float2(*(__half2*)&v.x);
                float2 f1 = __half22float2(*(__half2*)&v.y);
                float2 f2 = __half22float2(*(__half2*)&v.z);
                float2 f3 = __half22float2(*(__half2*)&v.w);
                acc[0] += f0.x; acc[1] += f0.y; acc[2] += f1.x; acc[3] += f1.y;
                acc[4] += f2.x; acc[5] += f2.y; acc[6] += f3.x; acc[7] += f3.y;
            }
        }
    }
#pragma unroll
    for (int c = 0; c < 8; c++) acc[c] += __shfl_xor_sync(0xffffffff, acc[c], 16);
    if (half == 0) {
        float r = 1.0f / fmaxf((float)(end - beg), 1.0f);
        __half2 p0 = __floats2half2_rn(acc[0] * r, acc[1] * r);
        __half2 p1 = __floats2half2_rn(acc[2] * r, acc[3] * r);
        __half2 p2 = __floats2half2_rn(acc[4] * r, acc[5] * r);
        __half2 p3 = __floats2half2_rn(acc[6] * r, acc[7] * r);
        uint4 u;
        u.x = *(unsigned*)&p0; u.y = *(unsigned*)&p1;
        u.z = *(unsigned*)&p2; u.w = *(unsigned*)&p3;
        ((uint4*)g_agg1)[(size_t)n * 16 + l16] = u;
    }
}

// layer-1 GEMM on tensor cores:
//   h = relu( concat(agg1, x) @ Wcat^T + b1 ),  fp16 operands, fp32 accum.
__global__ void __launch_bounds__(256) k_gemm1_mma(const float* __restrict__ b1) {
    __shared__ __half sA[128][72];   // 64 data halves + 8 pad
    __shared__ __half sW[128][72];
    __shared__ float  sb[128];

    int tid = threadIdx.x;
    int lane = tid & 31;
    int w = tid >> 5;
    int n0 = blockIdx.x * 128;

    if (tid < 128) sb[tid] = __ldg(&b1[tid]);

    float acc[16][4];
#pragma unroll
    for (int t = 0; t < 16; t++)
#pragma unroll
        for (int j = 0; j < 4; j++) acc[t][j] = 0.f;

    const uint4* A1 = (const uint4*)g_agg1;
    const uint4* AX = (const uint4*)g_xh;
    const uint4* WC = (const uint4*)g_Wcat;

    for (int c = 0; c < 4; c++) {
        for (int i = tid; i < 1024; i += 256) {
            int r = i >> 3, c8 = i & 7;
            int node = min(n0 + r, N_NODES - 1);
            uint4 va = (c < 2) ? __ldg(&A1[(size_t)node * 16 + c * 8 + c8])
                               : __ldg(&AX[(size_t)node * 16 + (c - 2) * 8 + c8]);
            *(uint4*)&sA[r][c8 * 8] = va;
            uint4 vw = __ldg(&WC[r * 32 + c * 8 + c8]);
            *(uint4*)&sW[r][c8 * 8] = vw;
        }
        __syncthreads();

#pragma unroll
        for (int ks = 0; ks < 4; ks++) {
            uint32_t a[4];
            int ar = w * 16 + (lane >> 2);
            int ah = ks * 16 + (lane & 3) * 2;
            a[0] = *(const uint32_t*)&sA[ar][ah];
            a[1] = *(const uint32_t*)&sA[ar + 8][ah];
            a[2] = *(const uint32_t*)&sA[ar][ah + 8];
            a[3] = *(const uint32_t*)&sA[ar + 8][ah + 8];
#pragma unroll
            for (int t = 0; t < 16; t++) {
                int br = t * 8 + (lane >> 2);
                uint32_t b0 = *(const uint32_t*)&sW[br][ah];
                uint32_t b1r = *(const uint32_t*)&sW[br][ah + 8];
                mma16816(acc[t], a, b0, b1r);
            }
        }
        __syncthreads();
    }

    int row = w * 16 + (lane >> 2);
    int node0 = n0 + row;
    int node1 = node0 + 8;
#pragma unroll
    for (int t = 0; t < 16; t++) {
        int col = t * 8 + (lane & 3) * 2;
        float b0f = sb[col], b1f = sb[col + 1];
        if (node0 < N_NODES) {
            __half2 p = __floats2half2_rn(fmaxf(acc[t][0] + b0f, 0.f),
                                          fmaxf(acc[t][1] + b1f, 0.f));
            *(uint32_t*)&g_h[(size_t)node0 * 128 + col] = *(uint32_t*)&p;
        }
        if (node1 < N_NODES) {
            __half2 p = __floats2half2_rn(fmaxf(acc[t][2] + b0f, 0.f),
                                          fmaxf(acc[t][3] + b1f, 0.f));
            *(uint32_t*)&g_h[(size_t)node1 * 128 + col] = *(uint32_t*)&p;
        }
    }
}

// layer-2 aggregation fused with pooling (warp per node), 2-edge uint4 gather
__global__ void k_agg2pool(const void* __restrict__ batch) {
    const int is64 = g_is64;
    int lane = threadIdx.x & 31;
    int n = (blockIdx.x * blockDim.x + threadIdx.x) >> 5;
    if (n >= N_NODES) return;
    int beg = g_rowptr[n], end = g_rowptr[n + 1];
    int half = lane >> 4, l16 = lane & 15;
    float acc[8] = {0.f, 0.f, 0.f, 0.f, 0.f, 0.f, 0.f, 0.f};
    const uint4* h4 = (const uint4*)g_h;
    for (int e0 = beg; e0 < end; e0 += 32) {
        int myc = (e0 + lane < end) ? g_col[e0 + lane] : -1;
        int m = min(32, end - e0);
        int npair = (m + 1) >> 1;
        for (int j = 0; j < npair; j++) {
            int s0 = __shfl_sync(0xffffffff, myc, 2 * j);
            int s1 = __shfl_sync(0xffffffff, myc, 2 * j + 1);
            int s = half ? s1 : s0;
            if (s >= 0) {
                uint4 v = __ldg(&h4[(size_t)s * 16 + l16]);
                float2 f0 = __half22float2(*(__half2*)&v.x);
                float2 f1 = __half22float2(*(__half2*)&v.y);
                float2 f2 = __half22float2(*(__half2*)&v.z);
                float2 f3 = __half22float2(*(__half2*)&v.w);
                acc[0] += f0.x; acc[1] += f0.y; acc[2] += f1.x; acc[3] += f1.y;
                acc[4] += f2.x; acc[5] += f2.y; acc[6] += f3.x; acc[7] += f3.y;
            }
        }
    }
#pragma unroll
    for (int c = 0; c < 8; c++) acc[c] += __shfl_xor_sync(0xffffffff, acc[c], 16);

    int g;
    if (is64) g = (int)((const long long*)batch)[n];
    else      g = ((const int*)batch)[n];
    g = min(max(g, 0), N_GRAPHS - 1);

    if (half == 0) {
        float r = 1.0f / fmaxf((float)(end - beg), 1.0f);
        float* pL = g_poolL + g * 128 + l16 * 8;
        asm volatile("red.global.add.v4.f32 [%0], {%1,%2,%3,%4};"
                     :: "l"(pL), "f"(acc[0] * r), "f"(acc[1] * r), "f"(acc[2] * r), "f"(acc[3] * r) : "memory");
        asm volatile("red.global.add.v4.f32 [%0], {%1,%2,%3,%4};"
                     :: "l"(pL + 4), "f"(acc[4] * r), "f"(acc[5] * r), "f"(acc[6] * r), "f"(acc[7] * r) : "memory");

        uint4 hv = __ldg(&h4[(size_t)n * 16 + l16]);
        float2 f0 = __half22float2(*(__half2*)&hv.x);
        float2 f1 = __half22float2(*(__half2*)&hv.y);
        float2 f2 = __half22float2(*(__half2*)&hv.z);
        float2 f3 = __half22float2(*(__half2*)&hv.w);
        float* pR = g_poolR + g * 128 + l16 * 8;
        asm volatile("red.global.add.v4.f32 [%0], {%1,%2,%3,%4};"
                     :: "l"(pR), "f"(f0.x), "f"(f0.y), "f"(f1.x), "f"(f1.y) : "memory");
        asm volatile("red.global.add.v4.f32 [%0], {%1,%2,%3,%4};"
                     :: "l"(pR + 4), "f"(f2.x), "f"(f2.y), "f"(f3.x), "f"(f3.y) : "memory");
        if (lane == 0) atomicAdd(&g_cnt[g], 1.0f);
    }
}

// final: out[g][o] = ( poolL[g]@Wl2[o]^T + poolR[g]@Wr2[o]^T ) / max(cnt,1) + b2[o]
__global__ void k_final(const float* __restrict__ Wl2, const float* __restrict__ Wr2,
                        const float* __restrict__ b2, float* __restrict__ out) {
    __shared__ float pl[128];
    __shared__ float pr[128];
    int g = blockIdx.x;
    int t = threadIdx.x;   // 64 threads
    pl[t]      = g_poolL[g * 128 + t];
    pl[t + 64] = g_poolL[g * 128 + t + 64];
    pr[t]      = g_poolR[g * 128 + t];
    pr[t + 64] = g_poolR[g * 128 + t + 64];
    __syncthreads();
    float c = fmaxf(g_cnt[g], 1.0f);
    float acc = 0.f;
    const float4* wl4 = (const float4*)&Wl2[t * 128];
    const float4* wr4 = (const float4*)&Wr2[t * 128];
#pragma unroll 8
    for (int k4 = 0; k4 < 32; k4++) {
        float4 wl = __ldg(&wl4[k4]);
        float4 wr = __ldg(&wr4[k4]);
        int k = 4 * k4;
        acc += pl[k]     * wl.x + pl[k + 1] * wl.y + pl[k + 2] * wl.z + pl[k + 3] * wl.w;
        acc += pr[k]     * wr.x + pr[k + 1] * wr.y + pr[k + 2] * wr.z + pr[k + 3] * wr.w;
    }
    out[g * 64 + t] = acc / c + __ldg(&b2[t]);
}

// ---------------- launch ----------------
extern "C" void kernel_launch(void* const* d_in, const int* in_sizes, int n_in,
                              void* d_out, int out_size) {
    const float* x     = (const float*)d_in[0];
    const void*  ei    = d_in[1];
    const void*  batch = d_in[2];
    const float* Wl1   = (const float*)d_in[3];
    const float* Wr1   = (const float*)d_in[4];
    const float* b1    = (const float*)d_in[5];
    const float* Wl2   = (const float*)d_in[6];
    const float* Wr2   = (const float*)d_in[7];
    const float* b2    = (const float*)d_in[8];
    float* out = (float*)d_out;

    // setup (zero + Wcat + x->fp16 + dtype detect)
    k_setup<<<2048, 256>>>((const int*)ei, Wl1, Wr1, (const float4*)x);

    // build CSR grouped by dst
    k_hist<<<2048, 256>>>(ei);
    k_scan1<<<(N_NODES + 1023) / 1024, 1024>>>();
    k_scan2<<<1, 128>>>();
    k_scan3<<<(N_NODES + 255) / 256, 256>>>();
    k_fill<<<2048, 256>>>(ei);

    // layer 1: gather-mean then tensor-core gemm+relu
    k_agg1<<<(N_NODES * 32 + 255) / 256, 256>>>();
    k_gemm1_mma<<<(N_NODES + 127) / 128, 256>>>(b1);

    // layer 2 aggregation fused with pooling
    k_agg2pool<<<(N_NODES * 32 + 255) / 256, 256>>>(batch);

    // tiny final GEMMs [256,128]x[128,64]
    k_final<<<N_GRAPHS, 64>>>(Wl2, Wr2, b2, out);
}

// round 10
// speedup vs baseline: 3.3565x; 1.0002x over previous
#include <cuda_runtime.h>
#include <cuda_fp16.h>
#include <cstdint>

#define N_NODES  100000
#define N_EDGES  3200000
#define N_GRAPHS 256
#define IN_DIM   128
#define HID_DIM  128
#define OUT_DIM  64

// ---------------- scratch (static device globals; no allocation) ----------------
__device__ __half g_xh  [(size_t)N_NODES * IN_DIM];   // 25.6 MB  x in fp16
__device__ __half g_agg1[(size_t)N_NODES * IN_DIM];   // 25.6 MB  layer-1 mean (fp16)
__device__ __half g_h   [(size_t)N_NODES * HID_DIM];  // 25.6 MB  hidden (fp16)
__device__ __half g_Wcat[HID_DIM * 256];              // [out][k] k = concat(Wl1, Wr1)
__device__ int   g_count [N_NODES];
__device__ int   g_rowptr[N_NODES + 1];
__device__ int   g_wcur  [N_NODES];
__device__ int   g_col   [N_EDGES];                   // CSR col = src, grouped by dst
__device__ int   g_bsum[128];
__device__ float g_poolL[N_GRAPHS * HID_DIM];
__device__ float g_poolR[N_GRAPHS * HID_DIM];
__device__ float g_cnt [N_GRAPHS];
__device__ int   g_is64;

__device__ __forceinline__ void mma16816(float* c, const uint32_t* a, uint32_t b0, uint32_t b1) {
    asm volatile(
        "mma.sync.aligned.m16n8k16.row.col.f32.f16.f16.f32 "
        "{%0,%1,%2,%3}, {%4,%5,%6,%7}, {%8,%9}, {%0,%1,%2,%3};"
        : "+f"(c[0]), "+f"(c[1]), "+f"(c[2]), "+f"(c[3])
        : "r"(a[0]), "r"(a[1]), "r"(a[2]), "r"(a[3]), "r"(b0), "r"(b1));
}

// ---------------- kernels ----------------

// setup: zero counters/pools, build fp16 Wcat, convert x -> fp16, detect dtype (block 0).
__global__ void k_setup(const int* __restrict__ ei32,
                        const float* __restrict__ Wl, const float* __restrict__ Wr,
                        const float4* __restrict__ x4) {
    int i = blockIdx.x * blockDim.x + threadIdx.x;
    int stride = gridDim.x * blockDim.x;
    for (int j = i; j < N_NODES; j += stride) g_count[j] = 0;
    for (int j = i; j < N_GRAPHS * HID_DIM; j += stride) { g_poolL[j] = 0.f; g_poolR[j] = 0.f; }
    if (i < N_GRAPHS) g_cnt[i] = 0.f;
    for (int j = i; j < HID_DIM * 256; j += stride) {
        int o = j >> 8, k = j & 255;
        float v = (k < 128) ? Wl[o * 128 + k] : Wr[o * 128 + (k - 128)];
        g_Wcat[o * 256 + k] = __float2half_rn(v);
    }
    // x fp32 -> fp16
    {
        uint2* dst = (uint2*)g_xh;
        const int total = N_NODES * IN_DIM / 4;
        for (int j = i; j < total; j += stride) {
            float4 v = __ldg(&x4[j]);
            __half2 h0 = __floats2half2_rn(v.x, v.y);
            __half2 h1 = __floats2half2_rn(v.z, v.w);
            uint2 u;
            u.x = *(unsigned*)&h0;
            u.y = *(unsigned*)&h1;
            dst[j] = u;
        }
    }
    if (blockIdx.x == 0) {
        __shared__ int any_nonzero;
        if (threadIdx.x == 0) any_nonzero = 0;
        __syncthreads();
        for (int j = threadIdx.x; j < 2048; j += blockDim.x) {
            long long pos = 2LL * ((long long)j * 1553LL + 1) + 1;  // odd words
            if (pos < 2LL * N_EDGES) {
                if (ei32[pos] != 0) atomicOr(&any_nonzero, 1);
            }
        }
        __syncthreads();
        if (threadIdx.x == 0) g_is64 = any_nonzero ? 0 : 1;
    }
}

// CSR build: histogram of dst (2 edges per thread, vector loads)
__global__ void k_hist(const void* __restrict__ ei) {
    const int is64 = g_is64;
    int i = blockIdx.x * blockDim.x + threadIdx.x;
    int stride = gridDim.x * blockDim.x;
    const int E2 = N_EDGES / 2;
    if (is64) {
        const longlong2* d2 = (const longlong2*)((const long long*)ei + N_EDGES);
        for (int e = i; e < E2; e += stride) {
            longlong2 v = __ldg(&d2[e]);
            int d0 = min(max((int)v.x, 0), N_NODES - 1);
            int d1 = min(max((int)v.y, 0), N_NODES - 1);
            atomicAdd(&g_count[d0], 1);
            atomicAdd(&g_count[d1], 1);
        }
    } else {
        const int2* d2 = (const int2*)((const int*)ei + N_EDGES);
        for (int e = i; e < E2; e += stride) {
            int2 v = __ldg(&d2[e]);
            int d0 = min(max(v.x, 0), N_NODES - 1);
            int d1 = min(max(v.y, 0), N_NODES - 1);
            atomicAdd(&g_count[d0], 1);
            atomicAdd(&g_count[d1], 1);
        }
    }
}

// scan phase 1: per-block (1024-elem) exclusive scan, coalesced
__global__ void k_scan1() {
    __shared__ int sh[1024];
    int t = threadIdx.x;
    int n = blockIdx.x * 1024 + t;
    int v = (n < N_NODES) ? g_count[n] : 0;
    sh[t] = v;
    __syncthreads();
    for (int off = 1; off < 1024; off <<= 1) {
        int u = (t >= off) ? sh[t - off] : 0;
        __syncthreads();
        sh[t] += u;
        __syncthreads();
    }
    if (n < N_NODES) g_rowptr[n] = sh[t] - v;   // exclusive within block
    if (t == 1023) g_bsum[blockIdx.x] = sh[1023];
}

// scan phase 2+3 merged: every block redundantly scans the 98 block sums in
// smem (trivial), then applies offsets and inits write cursors.
__global__ void k_scan3() {
    __shared__ int sincl[128];   // inclusive scan of block sums
    __shared__ int sorig[128];
    const int NB = (N_NODES + 1023) / 1024;   // 98
    int t = threadIdx.x;   // 256 threads
    if (t < 128) {
        int v = (t < NB) ? g_bsum[t] : 0;
        sincl[t] = v;
        sorig[t] = v;
    }
    __syncthreads();
    for (int off = 1; off < 128; off <<= 1) {
        int u = 0;
        if (t < 128 && t >= off) u = sincl[t - off];
        __syncthreads();
        if (t < 128) sincl[t] += u;
        __syncthreads();
    }
    int i = blockIdx.x * blockDim.x + t;
    if (i < N_NODES) {
        int blk = i >> 10;
        int excl = sincl[blk] - sorig[blk];
        int r = g_rowptr[i] + excl;
        g_rowptr[i] = r;
        g_wcur[i] = r;
    }
    if (i == 0) g_rowptr[N_NODES] = N_EDGES;
}

// CSR build: place src ids grouped by dst (2 edges per thread, vector loads)
__global__ void k_fill(const void* __restrict__ ei) {
    const int is64 = g_is64;
    int i = blockIdx.x * blockDim.x + threadIdx.x;
    int stride = gridDim.x * blockDim.x;
    const int E2 = N_EDGES / 2;
    if (is64) {
        const longlong2* s2 = (const longlong2*)ei;
        const longlong2* d2 = (const longlong2*)((const long long*)ei + N_EDGES);
        for (int e = i; e < E2; e += stride) {
            longlong2 sv = __ldg(&s2[e]);
            longlong2 dv = __ldg(&d2[e]);
            int s0 = min(max((int)sv.x, 0), N_NODES - 1);
            int s1 = min(max((int)sv.y, 0), N_NODES - 1);
            int d0 = min(max((int)dv.x, 0), N_NODES - 1);
            int d1 = min(max((int)dv.y, 0), N_NODES - 1);
            g_col[atomicAdd(&g_wcur[d0], 1)] = s0;
            g_col[atomicAdd(&g_wcur[d1], 1)] = s1;
        }
    } else {
        const int2* s2 = (const int2*)ei;
        const int2* d2 = (const int2*)((const int*)ei + N_EDGES);
        for (int e = i; e < E2; e += stride) {
            int2 sv = __ldg(&s2[e]);
            int2 dv = __ldg(&d2[e]);
            int s0 = min(max(sv.x, 0), N_NODES - 1);
            int s1 = min(max(sv.y, 0), N_NODES - 1);
            int d0 = min(max(dv.x, 0), N_NODES - 1);
            int d1 = min(max(dv.y, 0), N_NODES - 1);
            g_col[atomicAdd(&g_wcur[d0], 1)] = s0;
            g_col[atomicAdd(&g_wcur[d1], 1)] = s1;
        }
    }
}

// layer-1 aggregation (warp per node), 2 edges per warp-iter via uint4:
// lanes 0-15 handle even edges, lanes 16-31 odd edges; cross-half reduce at end.
__global__ void k_agg1() {
    int lane = threadIdx.x & 31;
    int n = (blockIdx.x * blockDim.x + threadIdx.x) >> 5;
    if (n >= N_NODES) return;
    int beg = g_rowptr[n], end = g_rowptr[n + 1];
    int half = lane >> 4, l16 = lane & 15;
    float acc[8] = {0.f, 0.f, 0.f, 0.f, 0.f, 0.f, 0.f, 0.f};
    const uint4* x4 = (const uint4*)g_xh;     // row = 16 uint4 (8 halves each)
    for (int e0 = beg; e0 < end; e0 += 32) {
        int myc = (e0 + lane < end) ? g_col[e0 + lane] : -1;
        int m = min(32, end - e0);
        int npair = (m + 1) >> 1;
        #pragma unroll 4
        for (int j = 0; j < npair; j++) {
            int s0 = __shfl_sync(0xffffffff, myc, 2 * j);
            int s1 = __shfl_sync(0xffffffff, myc, 2 * j + 1);
            int s = half ? s1 : s0;
            if (s >= 0) {
                uint4 v = __ldg(&x4[(size_t)s * 16 + l16]);
                float2 f0 = __half22float2(*(__half2*)&v.x);
                float2 f1 = __half22float2(*(__half2*)&v.y);
                float2 f2 = __half22float2(*(__half2*)&v.z);
                float2 f3 = __half22float2(*(__half2*)&v.w);
                acc[0] += f0.x; acc[1] += f0.y; acc[2] += f1.x; acc[3] += f1.y;
                acc[4] += f2.x; acc[5] += f2.y; acc[6] += f3.x; acc[7] += f3.y;
            }
        }
    }
#pragma unroll
    for (int c = 0; c < 8; c++) acc[c] += __shfl_xor_sync(0xffffffff, acc[c], 16);
    if (half == 0) {
        float r = 1.0f / fmaxf((float)(end - beg), 1.0f);
        __half2 p0 = __floats2half2_rn(acc[0] * r, acc[1] * r);
        __half2 p1 = __floats2half2_rn(acc[2] * r, acc[3] * r);
        __half2 p2 = __floats2half2_rn(acc[4] * r, acc[5] * r);
        __half2 p3 = __floats2half2_rn(acc[6] * r, acc[7] * r);
        uint4 u;
        u.x = *(unsigned*)&p0; u.y = *(unsigned*)&p1;
        u.z = *(unsigned*)&p2; u.w = *(unsigned*)&p3;
        ((uint4*)g_agg1)[(size_t)n * 16 + l16] = u;
    }
}

// layer-1 GEMM on tensor cores:
//   h = relu( concat(agg1, x) @ Wcat^T + b1 ),  fp16 operands, fp32 accum.
__global__ void __launch_bounds__(256) k_gemm1_mma(const float* __restrict__ b1) {
    __shared__ __half sA[128][72];   // 64 data halves + 8 pad
    __shared__ __half sW[128][72];
    __shared__ float  sb[128];

    int tid = threadIdx.x;
    int lane = tid & 31;
    int w = tid >> 5;
    int n0 = blockIdx.x * 128;

    if (tid < 128) sb[tid] = __ldg(&b1[tid]);

    float acc[16][4];
#pragma unroll
    for (int t = 0; t < 16; t++)
#pragma unroll
        for (int j = 0; j < 4; j++) acc[t][j] = 0.f;

    const uint4* A1 = (const uint4*)g_agg1;
    const uint4* AX = (const uint4*)g_xh;
    const uint4* WC = (const uint4*)g_Wcat;

    for (int c = 0; c < 4; c++) {
        for (int i = tid; i < 1024; i += 256) {
            int r = i >> 3, c8 = i & 7;
            int node = min(n0 + r, N_NODES - 1);
            uint4 va = (c < 2) ? __ldg(&A1[(size_t)node * 16 + c * 8 + c8])
                               : __ldg(&AX[(size_t)node * 16 + (c - 2) * 8 + c8]);
            *(uint4*)&sA[r][c8 * 8] = va;
            uint4 vw = __ldg(&WC[r * 32 + c * 8 + c8]);
            *(uint4*)&sW[r][c8 * 8] = vw;
        }
        __syncthreads();

#pragma unroll
        for (int ks = 0; ks < 4; ks++) {
            uint32_t a[4];
            int ar = w * 16 + (lane >> 2);
            int ah = ks * 16 + (lane & 3) * 2;
            a[0] = *(const uint32_t*)&sA[ar][ah];
            a[1] = *(const uint32_t*)&sA[ar + 8][ah];
            a[2] = *(const uint32_t*)&sA[ar][ah + 8];
            a[3] = *(const uint32_t*)&sA[ar + 8][ah + 8];
#pragma unroll
            for (int t = 0; t < 16; t++) {
                int br = t * 8 + (lane >> 2);
                uint32_t b0 = *(const uint32_t*)&sW[br][ah];
                uint32_t b1r = *(const uint32_t*)&sW[br][ah + 8];
                mma16816(acc[t], a, b0, b1r);
            }
        }
        __syncthreads();
    }

    int row = w * 16 + (lane >> 2);
    int node0 = n0 + row;
    int node1 = node0 + 8;
#pragma unroll
    for (int t = 0; t < 16; t++) {
        int col = t * 8 + (lane & 3) * 2;
        float b0f = sb[col], b1f = sb[col + 1];
        if (node0 < N_NODES) {
            __half2 p = __floats2half2_rn(fmaxf(acc[t][0] + b0f, 0.f),
                                          fmaxf(acc[t][1] + b1f, 0.f));
            *(uint32_t*)&g_h[(size_t)node0 * 128 + col] = *(uint32_t*)&p;
        }
        if (node1 < N_NODES) {
            __half2 p = __floats2half2_rn(fmaxf(acc[t][2] + b0f, 0.f),
                                          fmaxf(acc[t][3] + b1f, 0.f));
            *(uint32_t*)&g_h[(size_t)node1 * 128 + col] = *(uint32_t*)&p;
        }
    }
}

// layer-2 aggregation fused with pooling (warp per node), 2-edge uint4 gather
__global__ void k_agg2pool(const void* __restrict__ batch) {
    const int is64 = g_is64;
    int lane = threadIdx.x & 31;
    int n = (blockIdx.x * blockDim.x + threadIdx.x) >> 5;
    if (n >= N_NODES) return;
    int beg = g_rowptr[n], end = g_rowptr[n + 1];
    int half = lane >> 4, l16 = lane & 15;
    float acc[8] = {0.f, 0.f, 0.f, 0.f, 0.f, 0.f, 0.f, 0.f};
    const uint4* h4 = (const uint4*)g_h;
    for (int e0 = beg; e0 < end; e0 += 32) {
        int myc = (e0 + lane < end) ? g_col[e0 + lane] : -1;
        int m = min(32, end - e0);
        int npair = (m + 1) >> 1;
        #pragma unroll 4
        for (int j = 0; j < npair; j++) {
            int s0 = __shfl_sync(0xffffffff, myc, 2 * j);
            int s1 = __shfl_sync(0xffffffff, myc, 2 * j + 1);
            int s = half ? s1 : s0;
            if (s >= 0) {
                uint4 v = __ldg(&h4[(size_t)s * 16 + l16]);
                float2 f0 = __half22float2(*(__half2*)&v.x);
                float2 f1 = __half22float2(*(__half2*)&v.y);
                float2 f2 = __half22float2(*(__half2*)&v.z);
                float2 f3 = __half22float2(*(__half2*)&v.w);
                acc[0] += f0.x; acc[1] += f0.y; acc[2] += f1.x; acc[3] += f1.y;
                acc[4] += f2.x; acc[5] += f2.y; acc[6] += f3.x; acc[7] += f3.y;
            }
        }
    }
#pragma unroll
    for (int c = 0; c < 8; c++) acc[c] += __shfl_xor_sync(0xffffffff, acc[c], 16);

    int g;
    if (is64) g = (int)((const long long*)batch)[n];
    else      g = ((const int*)batch)[n];
    g = min(max(g, 0), N_GRAPHS - 1);

    if (half == 0) {
        float r = 1.0f / fmaxf((float)(end - beg), 1.0f);
        float* pL = g_poolL + g * 128 + l16 * 8;
        asm volatile("red.global.add.v4.f32 [%0], {%1,%2,%3,%4};"
                     :: "l"(pL), "f"(acc[0] * r), "f"(acc[1] * r), "f"(acc[2] * r), "f"(acc[3] * r) : "memory");
        asm volatile("red.global.add.v4.f32 [%0], {%1,%2,%3,%4};"
                     :: "l"(pL + 4), "f"(acc[4] * r), "f"(acc[5] * r), "f"(acc[6] * r), "f"(acc[7] * r) : "memory");

        uint4 hv = __ldg(&h4[(size_t)n * 16 + l16]);
        float2 f0 = __half22float2(*(__half2*)&hv.x);
        float2 f1 = __half22float2(*(__half2*)&hv.y);
        float2 f2 = __half22float2(*(__half2*)&hv.z);
        float2 f3 = __half22float2(*(__half2*)&hv.w);
        float* pR = g_poolR + g * 128 + l16 * 8;
        asm volatile("red.global.add.v4.f32 [%0], {%1,%2,%3,%4};"
                     :: "l"(pR), "f"(f0.x), "f"(f0.y), "f"(f1.x), "f"(f1.y) : "memory");
        asm volatile("red.global.add.v4.f32 [%0], {%1,%2,%3,%4};"
                     :: "l"(pR + 4), "f"(f2.x), "f"(f2.y), "f"(f3.x), "f"(f3.y) : "memory");
        if (lane == 0) atomicAdd(&g_cnt[g], 1.0f);
    }
}

// final: out[g][o] = ( poolL[g]@Wl2[o]^T + poolR[g]@Wr2[o]^T ) / max(cnt,1) + b2[o]
__global__ void k_final(const float* __restrict__ Wl2, const float* __restrict__ Wr2,
                        const float* __restrict__ b2, float* __restrict__ out) {
    __shared__ float pl[128];
    __shared__ float pr[128];
    int g = blockIdx.x;
    int t = threadIdx.x;   // 64 threads
    pl[t]      = g_poolL[g * 128 + t];
    pl[t + 64] = g_poolL[g * 128 + t + 64];
    pr[t]      = g_poolR[g * 128 + t];
    pr[t + 64] = g_poolR[g * 128 + t + 64];
    __syncthreads();
    float c = fmaxf(g_cnt[g], 1.0f);
    float acc = 0.f;
    const float4* wl4 = (const float4*)&Wl2[t * 128];
    const float4* wr4 = (const float4*)&Wr2[t * 128];
#pragma unroll 8
    for (int k4 = 0; k4 < 32; k4++) {
        float4 wl = __ldg(&wl4[k4]);
        float4 wr = __ldg(&wr4[k4]);
        int k = 4 * k4;
        acc += pl[k]     * wl.x + pl[k + 1] * wl.y + pl[k + 2] * wl.z + pl[k + 3] * wl.w;
        acc += pr[k]     * wr.x + pr[k + 1] * wr.y + pr[k + 2] * wr.z + pr[k + 3] * wr.w;
    }
    out[g * 64 + t] = acc / c + __ldg(&b2[t]);
}

// ---------------- launch ----------------
extern "C" void kernel_launch(void* const* d_in, const int* in_sizes, int n_in,
                              void* d_out, int out_size) {
    const float* x     = (const float*)d_in[0];
    const void*  ei    = d_in[1];
    const void*  batch = d_in[2];
    const float* Wl1   = (const float*)d_in[3];
    const float* Wr1   = (const float*)d_in[4];
    const float* b1    = (const float*)d_in[5];
    const float* Wl2   = (const float*)d_in[6];
    const float* Wr2   = (const float*)d_in[7];
    const float* b2    = (const float*)d_in[8];
    float* out = (float*)d_out;

    // setup (zero + Wcat + x->fp16 + dtype detect)
    k_setup<<<2048, 256>>>((const int*)ei, Wl1, Wr1, (const float4*)x);

    // build CSR grouped by dst
    k_hist<<<2048, 256>>>(ei);
    k_scan1<<<(N_NODES + 1023) / 1024, 1024>>>();
    k_scan3<<<(N_NODES + 255) / 256, 256>>>();
    k_fill<<<2048, 256>>>(ei);

    // layer 1: gather-mean then tensor-core gemm+relu
    k_agg1<<<(N_NODES * 32 + 255) / 256, 256>>>();
    k_gemm1_mma<<<(N_NODES + 127) / 128, 256>>>(b1);

    // layer 2 aggregation fused with pooling
    k_agg2pool<<<(N_NODES * 32 + 255) / 256, 256>>>(batch);

    // tiny final GEMMs [256,128]x[128,64]
    k_final<<<N_GRAPHS, 64>>>(Wl2, Wr2, b2, out);
}